// round 2
// baseline (speedup 1.0000x reference)
#include <cuda_runtime.h>
#include <stdint.h>

#define NN 100000
#define FD 128
#define HD 256

// Scratch (allocation-free rule: __device__ globals)
__device__ int   g_deg_out[NN];
__device__ int   g_deg_in[NN];
__device__ int   g_is64;
__device__ float g_h[(size_t)NN * FD];
__device__ float g_agg[(size_t)NN * FD];

// ---------------------------------------------------------------------------
// Detect whether edge index arrays are int64 or int32 (JAX x64 ambiguity).
// If int64 with values < 2^31, every high 32-bit word of the first samples is 0.
__global__ void k_detect(const int* __restrict__ srcw, int E) {
    if (blockIdx.x == 0 && threadIdx.x == 0) {
        int n = E < 256 ? E : 256;
        int is64 = 1;
        for (int i = 0; i < n; i++) {
            if (srcw[2 * i + 1] != 0) { is64 = 0; break; }
        }
        g_is64 = is64;
    }
}

__device__ __forceinline__ int load_idx(const void* p, int i) {
    if (g_is64) return (int)((const long long*)p)[i];
    return ((const int*)p)[i];
}

// ---------------------------------------------------------------------------
__global__ void k_zero_deg(int N) {
    int i = blockIdx.x * blockDim.x + threadIdx.x;
    if (i < N) { g_deg_out[i] = 0; g_deg_in[i] = 0; }
}

__global__ void k_count(const void* __restrict__ src, const void* __restrict__ dst, int E) {
    int i = blockIdx.x * blockDim.x + threadIdx.x;
    if (i < E) {
        atomicAdd(&g_deg_out[load_idx(src, i)], 1);
        atomicAdd(&g_deg_in[load_idx(dst, i)], 1);
    }
}

// h = features * rsqrt(max(deg_out,1));  agg = 0
__global__ void k_h(const float* __restrict__ feat, int N) {
    int i = blockIdx.x * blockDim.x + threadIdx.x;   // float4 index
    int total = N * (FD / 4);
    if (i < total) {
        int node = i / (FD / 4);
        float nm = rsqrtf(fmaxf((float)g_deg_out[node], 1.0f));
        float4 v = ((const float4*)feat)[i];
        v.x *= nm; v.y *= nm; v.z *= nm; v.w *= nm;
        ((float4*)g_h)[i] = v;
        ((float4*)g_agg)[i] = make_float4(0.f, 0.f, 0.f, 0.f);
    }
}

// One warp per edge: gather 128 floats of h[src], vector-atomic-add into agg[dst].
__global__ void k_scatter(const void* __restrict__ src, const void* __restrict__ dst, int E) {
    int gid = blockIdx.x * blockDim.x + threadIdx.x;
    int e = gid >> 5;
    int lane = gid & 31;
    if (e >= E) return;
    int s, d;
    if (g_is64) {
        s = (int)((const long long*)src)[e];
        d = (int)((const long long*)dst)[e];
    } else {
        s = ((const int*)src)[e];
        d = ((const int*)dst)[e];
    }
    float4 v = ((const float4*)g_h)[(size_t)s * (FD / 4) + lane];
    float* ap = g_agg + (size_t)d * FD + (lane << 2);
    asm volatile("red.global.add.v4.f32 [%0], {%1,%2,%3,%4};"
                 :: "l"(ap), "f"(v.x), "f"(v.y), "f"(v.z), "f"(v.w)
                 : "memory");
}

// ---------------------------------------------------------------------------
// Fused epilogue: per 32-node tile:
//   gcn = (agg * rsqrt(max(deg_in,1))) @ W + b
//   out = relu(LN(gcn)*gamma+beta) + feat @ skip_W + skip_b
// Block = 256 threads (8 warps). Warp ty owns rows ty*4..ty*4+3; lane tx owns
// cols {tx*4..tx*4+3} and {128+tx*4..128+tx*4+3} (conflict-free LDS.128).
// LN row reduction = intra-thread sum of 8 + warp shfl reduce over 32 lanes.
#define BK 8

__global__ __launch_bounds__(256, 2)
void k_epilogue(const float* __restrict__ feat, const float* __restrict__ Wm,
                const float* __restrict__ bvec, const float* __restrict__ gvec,
                const float* __restrict__ bevec, const float* __restrict__ sWm,
                const float* __restrict__ sbvec, float* __restrict__ out, int N)
{
    extern __shared__ float sm[];
    float* sAgg  = sm;                    // 32*128
    float* sFeat = sAgg + 32 * FD;        // 32*128
    float* sW    = sFeat + 32 * FD;       // BK*256
    float* sS    = sW + BK * HD;          // BK*256   total = 49152 B

    int t = threadIdx.x;
    int tx = t & 31, ty = t >> 5;
    int node0 = blockIdx.x << 5;

    // Stage A tiles (agg pre-scaled by norm_dst, and raw features)
    #pragma unroll
    for (int j = 0; j < 4; j++) {
        int idx = t + (j << 8);           // float4 index 0..1023
        int row = idx >> 5, c4 = idx & 31;
        int node = node0 + row;
        float4 va = make_float4(0.f, 0.f, 0.f, 0.f), vf = va;
        if (node < N) {
            va = ((const float4*)g_agg)[(size_t)node * (FD / 4) + c4];
            vf = ((const float4*)feat)[(size_t)node * (FD / 4) + c4];
            float nm = rsqrtf(fmaxf((float)g_deg_in[node], 1.0f));
            va.x *= nm; va.y *= nm; va.z *= nm; va.w *= nm;
        }
        ((float4*)sAgg)[idx] = va;
        ((float4*)sFeat)[idx] = vf;
    }

    float acc1[4][8], acc2[4][8];
    #pragma unroll
    for (int r = 0; r < 4; r++)
        #pragma unroll
        for (int c = 0; c < 8; c++) { acc1[r][c] = 0.f; acc2[r][c] = 0.f; }

    for (int kc = 0; kc < FD / BK; kc++) {
        const float4* Wp = (const float4*)(Wm  + kc * BK * HD);
        const float4* Sp = (const float4*)(sWm + kc * BK * HD);
        #pragma unroll
        for (int j = 0; j < (BK * HD / 4) / 256; j++) {   // 2 iters
            int idx = t + (j << 8);
            ((float4*)sW)[idx] = Wp[idx];
            ((float4*)sS)[idx] = Sp[idx];
        }
        __syncthreads();
        #pragma unroll
        for (int kk = 0; kk < BK; kk++) {
            const float* wr = sW + kk * HD;
            const float* sr = sS + kk * HD;
            float wv[8], sv[8];
            *(float4*)&wv[0] = *(const float4*)(wr + (tx << 2));
            *(float4*)&wv[4] = *(const float4*)(wr + 128 + (tx << 2));
            *(float4*)&sv[0] = *(const float4*)(sr + (tx << 2));
            *(float4*)&sv[4] = *(const float4*)(sr + 128 + (tx << 2));
            int k = kc * BK + kk;
            #pragma unroll
            for (int r = 0; r < 4; r++) {
                float a1 = sAgg[((ty << 2) + r) * FD + k];
                float a2 = sFeat[((ty << 2) + r) * FD + k];
                #pragma unroll
                for (int c = 0; c < 8; c++) {
                    acc1[r][c] = fmaf(a1, wv[c], acc1[r][c]);
                    acc2[r][c] = fmaf(a2, sv[c], acc2[r][c]);
                }
            }
        }
        __syncthreads();
    }

    // Column-constant vectors for this lane's 8 columns
    float bb[8], gg[8], be[8], sb[8];
    *(float4*)&bb[0] = *(const float4*)(bvec  + (tx << 2));
    *(float4*)&bb[4] = *(const float4*)(bvec  + 128 + (tx << 2));
    *(float4*)&gg[0] = *(const float4*)(gvec  + (tx << 2));
    *(float4*)&gg[4] = *(const float4*)(gvec  + 128 + (tx << 2));
    *(float4*)&be[0] = *(const float4*)(bevec + (tx << 2));
    *(float4*)&be[4] = *(const float4*)(bevec + 128 + (tx << 2));
    *(float4*)&sb[0] = *(const float4*)(sbvec + (tx << 2));
    *(float4*)&sb[4] = *(const float4*)(sbvec + 128 + (tx << 2));

    #pragma unroll
    for (int r = 0; r < 4; r++) {
        int node = node0 + (ty << 2) + r;
        if (node >= N) continue;
        #pragma unroll
        for (int c = 0; c < 8; c++) acc1[r][c] += bb[c];   // bias before LN

        float s = 0.f;
        #pragma unroll
        for (int c = 0; c < 8; c++) s += acc1[r][c];
        #pragma unroll
        for (int o = 16; o > 0; o >>= 1) s += __shfl_xor_sync(0xffffffffu, s, o);
        float mu = s * (1.0f / HD);

        float v = 0.f;
        #pragma unroll
        for (int c = 0; c < 8; c++) { float d0 = acc1[r][c] - mu; v += d0 * d0; }
        #pragma unroll
        for (int o = 16; o > 0; o >>= 1) v += __shfl_xor_sync(0xffffffffu, v, o);
        float inv = rsqrtf(v * (1.0f / HD) + 1e-5f);

        float ov[8];
        #pragma unroll
        for (int c = 0; c < 8; c++) {
            float ln = (acc1[r][c] - mu) * inv * gg[c] + be[c];
            ov[c] = fmaxf(ln, 0.0f) + acc2[r][c] + sb[c];
        }
        float* op = out + (size_t)node * HD;
        *(float4*)(op + (tx << 2))       = *(float4*)&ov[0];
        *(float4*)(op + 128 + (tx << 2)) = *(float4*)&ov[4];
    }
}

// ---------------------------------------------------------------------------
extern "C" void kernel_launch(void* const* d_in, const int* in_sizes, int n_in,
                              void* d_out, int out_size)
{
    const float* feat = (const float*)d_in[0];
    const void*  src  = d_in[1];
    const void*  dst  = d_in[2];
    const float* Wm   = (const float*)d_in[3];
    const float* bv   = (const float*)d_in[4];
    const float* gm   = (const float*)d_in[5];
    const float* bt   = (const float*)d_in[6];
    const float* sWm  = (const float*)d_in[7];
    const float* sbv  = (const float*)d_in[8];
    float* out = (float*)d_out;

    int N = in_sizes[0] / FD;
    int E = in_sizes[1];

    k_detect<<<1, 32>>>((const int*)src, E);
    k_zero_deg<<<(N + 255) / 256, 256>>>(N);
    k_count<<<(E + 255) / 256, 256>>>(src, dst, E);
    k_h<<<(N * (FD / 4) + 255) / 256, 256>>>(feat, N);

    long long sthreads = (long long)E * 32;
    int sblocks = (int)((sthreads + 255) / 256);
    k_scatter<<<sblocks, 256>>>(src, dst, E);

    k_epilogue<<<(N + 31) / 32, 256, 49152>>>(feat, Wm, bv, gm, bt, sWm, sbv, out, N);
}

// round 3
// speedup vs baseline: 1.6023x; 1.6023x over previous
#include <cuda_runtime.h>
#include <stdint.h>

#define NN 100000
#define EMAX 1700000
#define FD 128
#define HD 256

// ---------------- scratch (__device__ globals; no allocs allowed) ----------
__device__ int   g_deg_out[NN];
__device__ int   g_deg_in[NN];
__device__ int   g_is64;
__device__ float g_nsrc[NN];
__device__ float g_ndst[NN];
__device__ int   g_rowptr[NN + 1];
__device__ int   g_cursor[NN];
__device__ int   g_bsum[128];
__device__ int   g_bexc[128];
__device__ int   g_eidx[EMAX];
__device__ float g_agg[(size_t)NN * FD];
__device__ unsigned g_Wt0[FD * HD];   // W in tf32 bits
__device__ unsigned g_Wt1[FD * HD];   // skip_W in tf32 bits

// ---------------------------------------------------------------------------
__global__ void k_detect(const int* __restrict__ srcw, int E) {
    if (blockIdx.x == 0 && threadIdx.x == 0) {
        int n = E < 256 ? E : 256;
        int is64 = 1;
        for (int i = 0; i < n; i++)
            if (srcw[2 * i + 1] != 0) { is64 = 0; break; }
        g_is64 = is64;
    }
}

__device__ __forceinline__ int load_idx(const void* p, int i) {
    if (g_is64) return (int)((const long long*)p)[i];
    return ((const int*)p)[i];
}

__global__ void k_zero(int N) {
    int i = blockIdx.x * blockDim.x + threadIdx.x;
    if (i < N) { g_deg_out[i] = 0; g_deg_in[i] = 0; }
}

__global__ void k_count(const void* __restrict__ src, const void* __restrict__ dst, int E) {
    int i = blockIdx.x * blockDim.x + threadIdx.x;
    if (i < E) {
        atomicAdd(&g_deg_out[load_idx(src, i)], 1);
        atomicAdd(&g_deg_in[load_idx(dst, i)], 1);
    }
}

__global__ void k_norms(int N) {
    int i = blockIdx.x * blockDim.x + threadIdx.x;
    if (i < N) {
        g_nsrc[i] = rsqrtf(fmaxf((float)g_deg_out[i], 1.0f));
        g_ndst[i] = rsqrtf(fmaxf((float)g_deg_in[i], 1.0f));
    }
}

// --- exclusive scan of deg_in -> rowptr (3 phases) -------------------------
__global__ void k_scan1(int N) {
    __shared__ int s[1024];
    int tid = threadIdx.x;
    int i = blockIdx.x * 1024 + tid;
    int v = (i < N) ? g_deg_in[i] : 0;
    s[tid] = v;
    for (int off = 1; off < 1024; off <<= 1) {
        __syncthreads();
        int t = (tid >= off) ? s[tid - off] : 0;
        __syncthreads();
        s[tid] += t;
    }
    __syncthreads();
    if (i < N) g_rowptr[i] = s[tid] - v;       // exclusive within block
    if (tid == 1023) g_bsum[blockIdx.x] = s[1023];
}

__global__ void k_scan2(int nb) {
    __shared__ int s[128];
    int tid = threadIdx.x;
    int v = (tid < nb) ? g_bsum[tid] : 0;
    s[tid] = v;
    for (int off = 1; off < 128; off <<= 1) {
        __syncthreads();
        int t = (tid >= off) ? s[tid - off] : 0;
        __syncthreads();
        s[tid] += t;
    }
    __syncthreads();
    g_bexc[tid] = s[tid] - v;
}

__global__ void k_scan3(int N, int E) {
    int i = blockIdx.x * 1024 + threadIdx.x;
    if (i < N) {
        int val = g_rowptr[i] + g_bexc[blockIdx.x];
        g_rowptr[i] = val;
        g_cursor[i] = val;
    }
    if (i == 0) g_rowptr[N] = E;
}

__global__ void k_fill(const void* __restrict__ src, const void* __restrict__ dst, int E) {
    int i = blockIdx.x * blockDim.x + threadIdx.x;
    if (i < E) {
        int d = load_idx(dst, i);
        int pos = atomicAdd(&g_cursor[d], 1);
        g_eidx[pos] = load_idx(src, i);
    }
}

// warp per node: agg[n] = norm_dst[n] * sum_{e in CSR(n)} feat[src_e]*norm_src[src_e]
__global__ void k_gather(const float* __restrict__ feat, int N) {
    int w = (blockIdx.x * blockDim.x + threadIdx.x) >> 5;
    int lane = threadIdx.x & 31;
    if (w >= N) return;
    int beg = g_rowptr[w], end = g_rowptr[w + 1];
    float4 acc = make_float4(0.f, 0.f, 0.f, 0.f);
    for (int base = beg; base < end; base += 32) {
        int idx = base + lane;
        int mye = (idx < end) ? g_eidx[idx] : 0;
        int cnt = min(32, end - base);
        for (int i = 0; i < cnt; i++) {
            int s = __shfl_sync(0xffffffffu, mye, i);
            float ns = g_nsrc[s];
            float4 v = ((const float4*)feat)[(size_t)s * 32 + lane];
            acc.x = fmaf(v.x, ns, acc.x);
            acc.y = fmaf(v.y, ns, acc.y);
            acc.z = fmaf(v.z, ns, acc.z);
            acc.w = fmaf(v.w, ns, acc.w);
        }
    }
    float nd = g_ndst[w];
    acc.x *= nd; acc.y *= nd; acc.z *= nd; acc.w *= nd;
    ((float4*)g_agg)[(size_t)w * 32 + lane] = acc;
}

// convert weights to tf32 bits once
__global__ void k_prep(const float* __restrict__ W, const float* __restrict__ sW) {
    int i = blockIdx.x * blockDim.x + threadIdx.x;
    if (i < FD * HD) {
        unsigned a, b;
        asm("cvt.rna.tf32.f32 %0, %1;" : "=r"(a) : "f"(W[i]));
        asm("cvt.rna.tf32.f32 %0, %1;" : "=r"(b) : "f"(sW[i]));
        g_Wt0[i] = a;
        g_Wt1[i] = b;
    }
}

// ---------------------------------------------------------------------------
// TF32 MMA GEMM: block = 64 rows x 256 cols, K=128, 8 warps (4 row x 2 col),
// warp tile 16x128. A split hi+lo (2xTF32), B plain tf32.
__device__ __forceinline__ void mma_tf32(float* c, unsigned a0, unsigned a1,
                                         unsigned a2, unsigned a3,
                                         unsigned b0, unsigned b1) {
    asm volatile(
        "mma.sync.aligned.m16n8k8.row.col.f32.tf32.tf32.f32 "
        "{%0,%1,%2,%3}, {%4,%5,%6,%7}, {%8,%9}, {%0,%1,%2,%3};"
        : "+f"(c[0]), "+f"(c[1]), "+f"(c[2]), "+f"(c[3])
        : "r"(a0), "r"(a1), "r"(a2), "r"(a3), "r"(b0), "r"(b1));
}

template <bool DO_LN>
__global__ __launch_bounds__(256)
void k_gemm(const float* __restrict__ A, const unsigned* __restrict__ Bt,
            const float* __restrict__ bias, const float* __restrict__ gamma,
            const float* __restrict__ beta, float* __restrict__ out, int N)
{
    __shared__ float sAhi[64][20];
    __shared__ float sAlo[64][20];
    __shared__ float sB[16][264];
    __shared__ float2 sLN[64][2];

    int t = threadIdx.x;
    int lane = t & 31, wid = t >> 5;
    int wy = wid >> 1, wx = wid & 1;
    int n0 = blockIdx.x * 64;

    float acc[16][4];
#pragma unroll
    for (int i = 0; i < 16; i++)
#pragma unroll
        for (int j = 0; j < 4; j++) acc[i][j] = 0.f;

    int arow = t >> 2, aj = t & 3;

    for (int kc = 0; kc < 8; kc++) {
        // stage A chunk (64 x 16), split hi/lo tf32
        {
            int node = n0 + arow;
            float4 v = make_float4(0.f, 0.f, 0.f, 0.f);
            if (node < N)
                v = *(const float4*)(A + (size_t)node * FD + kc * 16 + aj * 4);
            float vv[4] = {v.x, v.y, v.z, v.w};
#pragma unroll
            for (int i = 0; i < 4; i++) {
                unsigned hb;
                asm("cvt.rna.tf32.f32 %0, %1;" : "=r"(hb) : "f"(vv[i]));
                float hf = __uint_as_float(hb);
                float lo = vv[i] - hf;
                unsigned lb;
                asm("cvt.rna.tf32.f32 %0, %1;" : "=r"(lb) : "f"(lo));
                sAhi[arow][aj * 4 + i] = __uint_as_float(hb);
                sAlo[arow][aj * 4 + i] = __uint_as_float(lb);
            }
        }
        // stage B chunk (16 x 256) from pre-converted tf32
#pragma unroll
        for (int j = 0; j < 16; j++) {
            int idx = t + j * 256;
            int k = idx >> 8, n = idx & 255;
            sB[k][n] = __uint_as_float(Bt[(kc * 16 + k) * HD + n]);
        }
        __syncthreads();

#pragma unroll
        for (int s = 0; s < 2; s++) {
            int kk = s * 8 + (lane & 3);
            int r0 = wy * 16 + (lane >> 2);
            unsigned ah0 = __float_as_uint(sAhi[r0][kk]);
            unsigned ah1 = __float_as_uint(sAhi[r0 + 8][kk]);
            unsigned ah2 = __float_as_uint(sAhi[r0][kk + 4]);
            unsigned ah3 = __float_as_uint(sAhi[r0 + 8][kk + 4]);
            unsigned al0 = __float_as_uint(sAlo[r0][kk]);
            unsigned al1 = __float_as_uint(sAlo[r0 + 8][kk]);
            unsigned al2 = __float_as_uint(sAlo[r0][kk + 4]);
            unsigned al3 = __float_as_uint(sAlo[r0 + 8][kk + 4]);
#pragma unroll
            for (int ni = 0; ni < 16; ni++) {
                int n = wx * 128 + ni * 8 + (lane >> 2);
                unsigned b0 = __float_as_uint(sB[kk][n]);
                unsigned b1 = __float_as_uint(sB[kk + 4][n]);
                mma_tf32(acc[ni], ah0, ah1, ah2, ah3, b0, b1);
                mma_tf32(acc[ni], al0, al1, al2, al3, b0, b1);
            }
        }
        __syncthreads();
    }

    // ---- epilogue ----
    int r0 = wy * 16 + (lane >> 2);          // local rows r0 (c0,c1), r0+8 (c2,c3)
    int colb = wx * 128 + 2 * (lane & 3);

    // add bias (before LN for the gcn kernel; skip_b for the skip kernel)
#pragma unroll
    for (int ni = 0; ni < 16; ni++) {
        float2 bb = *(const float2*)(bias + colb + ni * 8);
        acc[ni][0] += bb.x; acc[ni][1] += bb.y;
        acc[ni][2] += bb.x; acc[ni][3] += bb.y;
    }

    if (DO_LN) {
        float s1 = 0.f, q1 = 0.f, s2 = 0.f, q2 = 0.f;
#pragma unroll
        for (int ni = 0; ni < 16; ni++) {
            s1 += acc[ni][0] + acc[ni][1];
            q1 += acc[ni][0] * acc[ni][0] + acc[ni][1] * acc[ni][1];
            s2 += acc[ni][2] + acc[ni][3];
            q2 += acc[ni][2] * acc[ni][2] + acc[ni][3] * acc[ni][3];
        }
#pragma unroll
        for (int off = 1; off <= 2; off <<= 1) {
            s1 += __shfl_xor_sync(0xffffffffu, s1, off);
            q1 += __shfl_xor_sync(0xffffffffu, q1, off);
            s2 += __shfl_xor_sync(0xffffffffu, s2, off);
            q2 += __shfl_xor_sync(0xffffffffu, q2, off);
        }
        if ((lane & 3) == 0) {
            sLN[r0][wx] = make_float2(s1, q1);
            sLN[r0 + 8][wx] = make_float2(s2, q2);
        }
        __syncthreads();
        float2 pa = sLN[r0][0], pb = sLN[r0][1];
        float mu1 = (pa.x + pb.x) * (1.0f / HD);
        float var1 = (pa.y + pb.y) * (1.0f / HD) - mu1 * mu1;
        float inv1 = rsqrtf(var1 + 1e-5f);
        float2 pc = sLN[r0 + 8][0], pd = sLN[r0 + 8][1];
        float mu2 = (pc.x + pd.x) * (1.0f / HD);
        float var2 = (pc.y + pd.y) * (1.0f / HD) - mu2 * mu2;
        float inv2 = rsqrtf(var2 + 1e-5f);

        int node1 = n0 + r0, node2 = n0 + r0 + 8;
#pragma unroll
        for (int ni = 0; ni < 16; ni++) {
            int col = colb + ni * 8;
            float2 gm = *(const float2*)(gamma + col);
            float2 bt = *(const float2*)(beta + col);
            if (node1 < N) {
                float* op = out + (size_t)node1 * HD + col;
                float2 pv = *(float2*)op;
                float2 o;
                o.x = fmaxf((acc[ni][0] - mu1) * inv1 * gm.x + bt.x, 0.f) + pv.x;
                o.y = fmaxf((acc[ni][1] - mu1) * inv1 * gm.y + bt.y, 0.f) + pv.y;
                *(float2*)op = o;
            }
            if (node2 < N) {
                float* op = out + (size_t)node2 * HD + col;
                float2 pv = *(float2*)op;
                float2 o;
                o.x = fmaxf((acc[ni][2] - mu2) * inv2 * gm.x + bt.x, 0.f) + pv.x;
                o.y = fmaxf((acc[ni][3] - mu2) * inv2 * gm.y + bt.y, 0.f) + pv.y;
                *(float2*)op = o;
            }
        }
    } else {
        int node1 = n0 + r0, node2 = n0 + r0 + 8;
#pragma unroll
        for (int ni = 0; ni < 16; ni++) {
            int col = colb + ni * 8;
            if (node1 < N)
                *(float2*)(out + (size_t)node1 * HD + col) =
                    make_float2(acc[ni][0], acc[ni][1]);
            if (node2 < N)
                *(float2*)(out + (size_t)node2 * HD + col) =
                    make_float2(acc[ni][2], acc[ni][3]);
        }
    }
}

// ---------------------------------------------------------------------------
extern "C" void kernel_launch(void* const* d_in, const int* in_sizes, int n_in,
                              void* d_out, int out_size)
{
    const float* feat = (const float*)d_in[0];
    const void*  src  = d_in[1];
    const void*  dst  = d_in[2];
    const float* Wm   = (const float*)d_in[3];
    const float* bv   = (const float*)d_in[4];
    const float* gm   = (const float*)d_in[5];
    const float* bt   = (const float*)d_in[6];
    const float* sWm  = (const float*)d_in[7];
    const float* sbv  = (const float*)d_in[8];
    float* out = (float*)d_out;

    int N = in_sizes[0] / FD;
    int E = in_sizes[1];
    int nb = (N + 1023) / 1024;

    k_detect<<<1, 32>>>((const int*)src, E);
    k_zero<<<(N + 255) / 256, 256>>>(N);
    k_count<<<(E + 255) / 256, 256>>>(src, dst, E);
    k_norms<<<(N + 255) / 256, 256>>>(N);
    k_scan1<<<nb, 1024>>>(N);
    k_scan2<<<1, 128>>>(nb);
    k_scan3<<<nb, 1024>>>(N, E);
    k_fill<<<(E + 255) / 256, 256>>>(src, dst, E);
    k_gather<<<(N * 32 + 255) / 256, 256>>>(feat, N);
    k_prep<<<(FD * HD + 255) / 256, 256>>>(Wm, sWm);

    float* aggp = nullptr;
    cudaGetSymbolAddress((void**)&aggp, g_agg);
    unsigned* wt0 = nullptr;
    cudaGetSymbolAddress((void**)&wt0, g_Wt0);
    unsigned* wt1 = nullptr;
    cudaGetSymbolAddress((void**)&wt1, g_Wt1);

    int gblocks = (N + 63) / 64;
    // skip GEMM first: out = feat @ skip_W + skip_b
    k_gemm<false><<<gblocks, 256>>>(feat, wt1, sbv, nullptr, nullptr, out, N);
    // gcn GEMM + LN + ReLU + add: out += relu(LN(agg@W + b))
    k_gemm<true><<<gblocks, 256>>>(aggp, wt0, bv, gm, bt, out, N);
}

// round 4
// speedup vs baseline: 1.9268x; 1.2026x over previous
#include <cuda_runtime.h>
#include <stdint.h>

#define NN 100000
#define EMAX 1700000
#define FD 128
#define HD 256

// ---------------- scratch (__device__ globals; no allocs allowed) ----------
__device__ int   g_deg_out[NN];
__device__ int   g_deg_in[NN];
__device__ int   g_is64;
__device__ float g_nsrc[NN];
__device__ float g_ndst[NN];
__device__ int   g_rowptr[NN + 1];
__device__ int   g_cursor[NN];
__device__ int   g_bsum[128];
__device__ int   g_bexc[128];
__device__ int   g_eidx[EMAX];
__device__ float g_agg[(size_t)NN * FD];
__device__ unsigned g_Wt0[FD * HD];   // W in tf32 bits
__device__ unsigned g_Wt1[FD * HD];   // skip_W in tf32 bits

// ---------------------------------------------------------------------------
// Parallel int64-vs-int32 detection (one block, 256 threads).
__global__ void k_detect(const int* __restrict__ srcw, int E) {
    __shared__ int bad;
    if (threadIdx.x == 0) bad = 0;
    __syncthreads();
    int n = E / 2; if (n > 256) n = 256;
    if ((int)threadIdx.x < n && srcw[2 * threadIdx.x + 1] != 0) bad = 1;
    __syncthreads();
    if (threadIdx.x == 0) g_is64 = (bad == 0);
}

__device__ __forceinline__ int load_idx(const void* p, int i) {
    if (g_is64) return (int)((const long long*)p)[i];
    return ((const int*)p)[i];
}

__global__ void k_zero(int N) {
    int i = blockIdx.x * blockDim.x + threadIdx.x;
    if (i < N) { g_deg_out[i] = 0; g_deg_in[i] = 0; }
}

__global__ void k_count(const void* __restrict__ src, const void* __restrict__ dst, int E) {
    int i = blockIdx.x * blockDim.x + threadIdx.x;
    if (i < E) {
        atomicAdd(&g_deg_out[load_idx(src, i)], 1);
        atomicAdd(&g_deg_in[load_idx(dst, i)], 1);
    }
}

__global__ void k_norms(int N) {
    int i = blockIdx.x * blockDim.x + threadIdx.x;
    if (i < N) {
        g_nsrc[i] = rsqrtf(fmaxf((float)g_deg_out[i], 1.0f));
        g_ndst[i] = rsqrtf(fmaxf((float)g_deg_in[i], 1.0f));
    }
}

// --- exclusive scan of deg_in -> rowptr (3 phases) -------------------------
__global__ void k_scan1(int N) {
    __shared__ int s[1024];
    int tid = threadIdx.x;
    int i = blockIdx.x * 1024 + tid;
    int v = (i < N) ? g_deg_in[i] : 0;
    s[tid] = v;
    for (int off = 1; off < 1024; off <<= 1) {
        __syncthreads();
        int t = (tid >= off) ? s[tid - off] : 0;
        __syncthreads();
        s[tid] += t;
    }
    __syncthreads();
    if (i < N) g_rowptr[i] = s[tid] - v;
    if (tid == 1023) g_bsum[blockIdx.x] = s[1023];
}

__global__ void k_scan2(int nb) {
    __shared__ int s[128];
    int tid = threadIdx.x;
    int v = (tid < nb) ? g_bsum[tid] : 0;
    s[tid] = v;
    for (int off = 1; off < 128; off <<= 1) {
        __syncthreads();
        int t = (tid >= off) ? s[tid - off] : 0;
        __syncthreads();
        s[tid] += t;
    }
    __syncthreads();
    g_bexc[tid] = s[tid] - v;
}

__global__ void k_scan3(int N, int E) {
    int i = blockIdx.x * 1024 + threadIdx.x;
    if (i < N) {
        int val = g_rowptr[i] + g_bexc[blockIdx.x];
        g_rowptr[i] = val;
        g_cursor[i] = val;
    }
    if (i == 0) g_rowptr[N] = E;
}

__global__ void k_fill(const void* __restrict__ src, const void* __restrict__ dst, int E) {
    int i = blockIdx.x * blockDim.x + threadIdx.x;
    if (i < E) {
        int d = load_idx(dst, i);
        int pos = atomicAdd(&g_cursor[d], 1);
        g_eidx[pos] = load_idx(src, i);
    }
}

// warp per node: agg[n] = norm_dst[n] * sum_{e in CSR(n)} feat[src_e]*norm_src[src_e]
__global__ void k_gather(const float* __restrict__ feat, int N) {
    int w = (blockIdx.x * blockDim.x + threadIdx.x) >> 5;
    int lane = threadIdx.x & 31;
    if (w >= N) return;
    int beg = g_rowptr[w], end = g_rowptr[w + 1];
    float4 acc = make_float4(0.f, 0.f, 0.f, 0.f);
    for (int base = beg; base < end; base += 32) {
        int idx = base + lane;
        int mye = (idx < end) ? g_eidx[idx] : 0;
        int cnt = min(32, end - base);
        for (int i = 0; i < cnt; i++) {
            int s = __shfl_sync(0xffffffffu, mye, i);
            float ns = g_nsrc[s];
            float4 v = ((const float4*)feat)[(size_t)s * 32 + lane];
            acc.x = fmaf(v.x, ns, acc.x);
            acc.y = fmaf(v.y, ns, acc.y);
            acc.z = fmaf(v.z, ns, acc.z);
            acc.w = fmaf(v.w, ns, acc.w);
        }
    }
    float nd = g_ndst[w];
    acc.x *= nd; acc.y *= nd; acc.z *= nd; acc.w *= nd;
    ((float4*)g_agg)[(size_t)w * 32 + lane] = acc;
}

// convert weights to tf32 bits once
__global__ void k_prep(const float* __restrict__ W, const float* __restrict__ sW) {
    int i = blockIdx.x * blockDim.x + threadIdx.x;
    if (i < FD * HD) {
        unsigned a, b;
        asm("cvt.rna.tf32.f32 %0, %1;" : "=r"(a) : "f"(W[i]));
        asm("cvt.rna.tf32.f32 %0, %1;" : "=r"(b) : "f"(sW[i]));
        g_Wt0[i] = a;
        g_Wt1[i] = b;
    }
}

// ---------------------------------------------------------------------------
__device__ __forceinline__ void mma_tf32(float* c, unsigned a0, unsigned a1,
                                         unsigned a2, unsigned a3,
                                         unsigned b0, unsigned b1) {
    asm volatile(
        "mma.sync.aligned.m16n8k8.row.col.f32.tf32.tf32.f32 "
        "{%0,%1,%2,%3}, {%4,%5,%6,%7}, {%8,%9}, {%0,%1,%2,%3};"
        : "+f"(c[0]), "+f"(c[1]), "+f"(c[2]), "+f"(c[3])
        : "r"(a0), "r"(a1), "r"(a2), "r"(a3), "r"(b0), "r"(b1));
}

// Fused dual-GEMM + LN + ReLU + skip-add. Block = 64 rows x 256 cols, K=128.
// 8 warps: wy in 0..3 (16-row slices), wx in 0..1 (128-col halves), 16 n-frags
// per warp per matrix. Single-pass tf32 (B-rounding dominates error anyway).
__global__ __launch_bounds__(256)
void k_fused(const float* __restrict__ feat, const float* __restrict__ agg,
             const unsigned* __restrict__ Wt0, const unsigned* __restrict__ Wt1,
             const float* __restrict__ bias, const float* __restrict__ gamma,
             const float* __restrict__ beta, const float* __restrict__ sbias,
             float* __restrict__ out, int N)
{
    __shared__ float sA[64][20];     // agg chunk (tf32 bits as float)
    __shared__ float sF[64][20];     // feat chunk
    __shared__ float sW[16][264];    // W chunk
    __shared__ float sS[16][264];    // skip_W chunk
    __shared__ float2 sLN[64][2];

    int t = threadIdx.x;
    int lane = t & 31, wid = t >> 5;
    int wy = wid >> 1, wx = wid & 1;
    int n0 = blockIdx.x * 64;

    float accG[16][4], accS[16][4];
#pragma unroll
    for (int i = 0; i < 16; i++)
#pragma unroll
        for (int j = 0; j < 4; j++) { accG[i][j] = 0.f; accS[i][j] = 0.f; }

    int arow = t >> 2, aj = t & 3;

    for (int kc = 0; kc < 8; kc++) {
        // stage A chunks (64 x 16) for both matrices, converted to tf32
        {
            int node = n0 + arow;
            float4 va = make_float4(0.f, 0.f, 0.f, 0.f), vf = va;
            if (node < N) {
                va = *(const float4*)(agg  + (size_t)node * FD + kc * 16 + aj * 4);
                vf = *(const float4*)(feat + (size_t)node * FD + kc * 16 + aj * 4);
            }
            float av[4] = {va.x, va.y, va.z, va.w};
            float fv[4] = {vf.x, vf.y, vf.z, vf.w};
#pragma unroll
            for (int i = 0; i < 4; i++) {
                unsigned ab, fb;
                asm("cvt.rna.tf32.f32 %0, %1;" : "=r"(ab) : "f"(av[i]));
                asm("cvt.rna.tf32.f32 %0, %1;" : "=r"(fb) : "f"(fv[i]));
                sA[arow][aj * 4 + i] = __uint_as_float(ab);
                sF[arow][aj * 4 + i] = __uint_as_float(fb);
            }
        }
        // stage B chunks (16 x 256) for both weight matrices
#pragma unroll
        for (int j = 0; j < 16; j++) {
            int idx = t + j * 256;
            int k = idx >> 8, n = idx & 255;
            sW[k][n] = __uint_as_float(Wt0[(kc * 16 + k) * HD + n]);
            sS[k][n] = __uint_as_float(Wt1[(kc * 16 + k) * HD + n]);
        }
        __syncthreads();

#pragma unroll
        for (int s = 0; s < 2; s++) {
            int kk = s * 8 + (lane & 3);
            int r0 = wy * 16 + (lane >> 2);
            unsigned aG0 = __float_as_uint(sA[r0][kk]);
            unsigned aG1 = __float_as_uint(sA[r0 + 8][kk]);
            unsigned aG2 = __float_as_uint(sA[r0][kk + 4]);
            unsigned aG3 = __float_as_uint(sA[r0 + 8][kk + 4]);
            unsigned aF0 = __float_as_uint(sF[r0][kk]);
            unsigned aF1 = __float_as_uint(sF[r0 + 8][kk]);
            unsigned aF2 = __float_as_uint(sF[r0][kk + 4]);
            unsigned aF3 = __float_as_uint(sF[r0 + 8][kk + 4]);
#pragma unroll
            for (int ni = 0; ni < 16; ni++) {
                int n = wx * 128 + ni * 8 + (lane >> 2);
                unsigned w0 = __float_as_uint(sW[kk][n]);
                unsigned w1 = __float_as_uint(sW[kk + 4][n]);
                mma_tf32(accG[ni], aG0, aG1, aG2, aG3, w0, w1);
                unsigned s0 = __float_as_uint(sS[kk][n]);
                unsigned s1 = __float_as_uint(sS[kk + 4][n]);
                mma_tf32(accS[ni], aF0, aF1, aF2, aF3, s0, s1);
            }
        }
        __syncthreads();
    }

    // ---- epilogue ----
    int r0 = wy * 16 + (lane >> 2);
    int colb = wx * 128 + 2 * (lane & 3);

#pragma unroll
    for (int ni = 0; ni < 16; ni++) {
        float2 bb = *(const float2*)(bias + colb + ni * 8);
        float2 sb = *(const float2*)(sbias + colb + ni * 8);
        accG[ni][0] += bb.x; accG[ni][1] += bb.y;
        accG[ni][2] += bb.x; accG[ni][3] += bb.y;
        accS[ni][0] += sb.x; accS[ni][1] += sb.y;
        accS[ni][2] += sb.x; accS[ni][3] += sb.y;
    }

    // LN row statistics over accG
    float s1 = 0.f, q1 = 0.f, s2 = 0.f, q2 = 0.f;
#pragma unroll
    for (int ni = 0; ni < 16; ni++) {
        s1 += accG[ni][0] + accG[ni][1];
        q1 += accG[ni][0] * accG[ni][0] + accG[ni][1] * accG[ni][1];
        s2 += accG[ni][2] + accG[ni][3];
        q2 += accG[ni][2] * accG[ni][2] + accG[ni][3] * accG[ni][3];
    }
#pragma unroll
    for (int off = 1; off <= 2; off <<= 1) {
        s1 += __shfl_xor_sync(0xffffffffu, s1, off);
        q1 += __shfl_xor_sync(0xffffffffu, q1, off);
        s2 += __shfl_xor_sync(0xffffffffu, s2, off);
        q2 += __shfl_xor_sync(0xffffffffu, q2, off);
    }
    if ((lane & 3) == 0) {
        sLN[r0][wx] = make_float2(s1, q1);
        sLN[r0 + 8][wx] = make_float2(s2, q2);
    }
    __syncthreads();
    float2 pa = sLN[r0][0], pb = sLN[r0][1];
    float mu1 = (pa.x + pb.x) * (1.0f / HD);
    float var1 = (pa.y + pb.y) * (1.0f / HD) - mu1 * mu1;
    float inv1 = rsqrtf(var1 + 1e-5f);
    float2 pc = sLN[r0 + 8][0], pd = sLN[r0 + 8][1];
    float mu2 = (pc.x + pd.x) * (1.0f / HD);
    float var2 = (pc.y + pd.y) * (1.0f / HD) - mu2 * mu2;
    float inv2 = rsqrtf(var2 + 1e-5f);

    int node1 = n0 + r0, node2 = n0 + r0 + 8;
#pragma unroll
    for (int ni = 0; ni < 16; ni++) {
        int col = colb + ni * 8;
        float2 gm = *(const float2*)(gamma + col);
        float2 bt = *(const float2*)(beta + col);
        if (node1 < N) {
            float2 o;
            o.x = fmaxf((accG[ni][0] - mu1) * inv1 * gm.x + bt.x, 0.f) + accS[ni][0];
            o.y = fmaxf((accG[ni][1] - mu1) * inv1 * gm.y + bt.y, 0.f) + accS[ni][1];
            *(float2*)(out + (size_t)node1 * HD + col) = o;
        }
        if (node2 < N) {
            float2 o;
            o.x = fmaxf((accG[ni][2] - mu2) * inv2 * gm.x + bt.x, 0.f) + accS[ni][2];
            o.y = fmaxf((accG[ni][3] - mu2) * inv2 * gm.y + bt.y, 0.f) + accS[ni][3];
            *(float2*)(out + (size_t)node2 * HD + col) = o;
        }
    }
}

// ---------------------------------------------------------------------------
extern "C" void kernel_launch(void* const* d_in, const int* in_sizes, int n_in,
                              void* d_out, int out_size)
{
    const float* feat = (const float*)d_in[0];
    const void*  src  = d_in[1];
    const void*  dst  = d_in[2];
    const float* Wm   = (const float*)d_in[3];
    const float* bv   = (const float*)d_in[4];
    const float* gm   = (const float*)d_in[5];
    const float* bt   = (const float*)d_in[6];
    const float* sWm  = (const float*)d_in[7];
    const float* sbv  = (const float*)d_in[8];
    float* out = (float*)d_out;

    int N = in_sizes[0] / FD;
    int E = in_sizes[1];
    int nb = (N + 1023) / 1024;

    k_detect<<<1, 256>>>((const int*)src, E);
    k_zero<<<(N + 255) / 256, 256>>>(N);
    k_count<<<(E + 255) / 256, 256>>>(src, dst, E);
    k_norms<<<(N + 255) / 256, 256>>>(N);
    k_scan1<<<nb, 1024>>>(N);
    k_scan2<<<1, 128>>>(nb);
    k_scan3<<<nb, 1024>>>(N, E);
    k_fill<<<(E + 255) / 256, 256>>>(src, dst, E);
    k_gather<<<(N * 32 + 255) / 256, 256>>>(feat, N);
    k_prep<<<(FD * HD + 255) / 256, 256>>>(Wm, sWm);

    float* aggp = nullptr;
    cudaGetSymbolAddress((void**)&aggp, g_agg);
    unsigned* wt0 = nullptr;
    cudaGetSymbolAddress((void**)&wt0, g_Wt0);
    unsigned* wt1 = nullptr;
    cudaGetSymbolAddress((void**)&wt1, g_Wt1);

    k_fused<<<(N + 63) / 64, 256>>>(feat, aggp, wt0, wt1, bv, gm, bt, sbv, out, N);
}

// round 6
// speedup vs baseline: 1.9477x; 1.0108x over previous
#include <cuda_runtime.h>
#include <stdint.h>

#define NN 100000
#define EMAX 1700000
#define FD 128
#define HD 256

// ---------------- scratch (__device__ globals; no allocs allowed) ----------
__device__ int   g_deg_out[NN];
__device__ int   g_deg_in[NN];
__device__ int   g_is64;
__device__ float g_nsrc[NN];
__device__ float g_ndst[NN];
__device__ int   g_rowptr[NN + 1];
__device__ int   g_cursor[NN];
__device__ int   g_bsum[128];
__device__ int   g_bexc[128];
__device__ int   g_eidx[EMAX];
__device__ float g_agg[(size_t)NN * FD];
__device__ unsigned g_Wt0[FD * HD];   // W in tf32 bits
__device__ unsigned g_Wt1[FD * HD];   // skip_W in tf32 bits

// ---------------------------------------------------------------------------
// init: zero degree arrays; block 0 also detects int64-vs-int32 indices.
__global__ void k_init(const int* __restrict__ srcw, int E, int N) {
    int i = blockIdx.x * blockDim.x + threadIdx.x;
    if (i < N) { g_deg_out[i] = 0; g_deg_in[i] = 0; }
    if (blockIdx.x == 0) {
        __shared__ int bad;
        if (threadIdx.x == 0) bad = 0;
        __syncthreads();
        int n = E / 2; if (n > 256) n = 256;
        if ((int)threadIdx.x < n && srcw[2 * threadIdx.x + 1] != 0) bad = 1;
        __syncthreads();
        if (threadIdx.x == 0) g_is64 = (bad == 0);
    }
}

__device__ __forceinline__ int load_idx(const void* p, int i) {
    if (g_is64) return (int)((const long long*)p)[i];
    return ((const int*)p)[i];
}

__global__ void k_count(const void* __restrict__ src, const void* __restrict__ dst, int E) {
    int i = (blockIdx.x * blockDim.x + threadIdx.x) * 2;
    if (i < E) {
        atomicAdd(&g_deg_out[load_idx(src, i)], 1);
        atomicAdd(&g_deg_in[load_idx(dst, i)], 1);
        if (i + 1 < E) {
            atomicAdd(&g_deg_out[load_idx(src, i + 1)], 1);
            atomicAdd(&g_deg_in[load_idx(dst, i + 1)], 1);
        }
    }
}

// --- exclusive scan of deg_in -> rowptr (3 phases); phase 1 also does norms --
__global__ void k_scan1(int N) {
    __shared__ int s[1024];
    int tid = threadIdx.x;
    int i = blockIdx.x * 1024 + tid;
    int v = 0;
    if (i < N) {
        int din = g_deg_in[i];
        v = din;
        g_nsrc[i] = rsqrtf(fmaxf((float)g_deg_out[i], 1.0f));
        g_ndst[i] = rsqrtf(fmaxf((float)din, 1.0f));
    }
    s[tid] = v;
    for (int off = 1; off < 1024; off <<= 1) {
        __syncthreads();
        int t = (tid >= off) ? s[tid - off] : 0;
        __syncthreads();
        s[tid] += t;
    }
    __syncthreads();
    if (i < N) g_rowptr[i] = s[tid] - v;
    if (tid == 1023) g_bsum[blockIdx.x] = s[1023];
}

__global__ void k_scan2(int nb) {
    __shared__ int s[128];
    int tid = threadIdx.x;
    int v = (tid < nb) ? g_bsum[tid] : 0;
    s[tid] = v;
    for (int off = 1; off < 128; off <<= 1) {
        __syncthreads();
        int t = (tid >= off) ? s[tid - off] : 0;
        __syncthreads();
        s[tid] += t;
    }
    __syncthreads();
    g_bexc[tid] = s[tid] - v;
}

__global__ void k_scan3(int N, int E) {
    int i = blockIdx.x * 1024 + threadIdx.x;
    if (i < N) {
        int val = g_rowptr[i] + g_bexc[blockIdx.x];
        g_rowptr[i] = val;
        g_cursor[i] = val;
    }
    if (i == 0) g_rowptr[N] = E;
}

__global__ void k_fill(const void* __restrict__ src, const void* __restrict__ dst, int E) {
    int i = blockIdx.x * blockDim.x + threadIdx.x;
    if (i < E) {
        int d = load_idx(dst, i);
        int pos = atomicAdd(&g_cursor[d], 1);
        g_eidx[pos] = load_idx(src, i);
    }
}

// warp per node: agg[n] = norm_dst[n] * sum_{e in CSR(n)} feat[src_e]*norm_src[src_e]
__global__ void k_gather(const float* __restrict__ feat, int N) {
    int w = (blockIdx.x * blockDim.x + threadIdx.x) >> 5;
    int lane = threadIdx.x & 31;
    if (w >= N) return;
    int beg = g_rowptr[w], end = g_rowptr[w + 1];
    float4 acc = make_float4(0.f, 0.f, 0.f, 0.f);
    for (int base = beg; base < end; base += 32) {
        int idx = base + lane;
        int mye = (idx < end) ? g_eidx[idx] : 0;
        int cnt = min(32, end - base);
        for (int i = 0; i < cnt; i++) {
            int s = __shfl_sync(0xffffffffu, mye, i);
            float ns = g_nsrc[s];
            float4 v = ((const float4*)feat)[(size_t)s * 32 + lane];
            acc.x = fmaf(v.x, ns, acc.x);
            acc.y = fmaf(v.y, ns, acc.y);
            acc.z = fmaf(v.z, ns, acc.z);
            acc.w = fmaf(v.w, ns, acc.w);
        }
    }
    float nd = g_ndst[w];
    acc.x *= nd; acc.y *= nd; acc.z *= nd; acc.w *= nd;
    ((float4*)g_agg)[(size_t)w * 32 + lane] = acc;
}

// convert weights to tf32 bits once
__global__ void k_prep(const float* __restrict__ W, const float* __restrict__ sW) {
    int i = blockIdx.x * blockDim.x + threadIdx.x;
    if (i < FD * HD) {
        unsigned a, b;
        asm("cvt.rna.tf32.f32 %0, %1;" : "=r"(a) : "f"(W[i]));
        asm("cvt.rna.tf32.f32 %0, %1;" : "=r"(b) : "f"(sW[i]));
        g_Wt0[i] = a;
        g_Wt1[i] = b;
    }
}

// ---------------------------------------------------------------------------
__device__ __forceinline__ void mma_tf32(float* c, unsigned a0, unsigned a1,
                                         unsigned a2, unsigned a3,
                                         unsigned b0, unsigned b1) {
    asm volatile(
        "mma.sync.aligned.m16n8k8.row.col.f32.tf32.tf32.f32 "
        "{%0,%1,%2,%3}, {%4,%5,%6,%7}, {%8,%9}, {%0,%1,%2,%3};"
        : "+f"(c[0]), "+f"(c[1]), "+f"(c[2]), "+f"(c[3])
        : "r"(a0), "r"(a1), "r"(a2), "r"(a3), "r"(b0), "r"(b1));
}

// Fused dual-GEMM + LN + ReLU + skip-add. Block = 64 rows x 256 cols, K=128.
__global__ __launch_bounds__(256)
void k_fused(const float* __restrict__ feat, const float* __restrict__ agg,
             const unsigned* __restrict__ Wt0, const unsigned* __restrict__ Wt1,
             const float* __restrict__ bias, const float* __restrict__ gamma,
             const float* __restrict__ beta, const float* __restrict__ sbias,
             float* __restrict__ out, int N)
{
    __shared__ float sA[64][20];     // agg chunk (tf32 bits as float)
    __shared__ float sF[64][20];     // feat chunk
    __shared__ float sW[16][264];    // W chunk
    __shared__ float sS[16][264];    // skip_W chunk
    __shared__ float2 sLN[64][2];

    int t = threadIdx.x;
    int lane = t & 31, wid = t >> 5;
    int wy = wid >> 1, wx = wid & 1;
    int n0 = blockIdx.x * 64;

    float accG[16][4], accS[16][4];
#pragma unroll
    for (int i = 0; i < 16; i++)
#pragma unroll
        for (int j = 0; j < 4; j++) { accG[i][j] = 0.f; accS[i][j] = 0.f; }

    int arow = t >> 2, aj = t & 3;

    for (int kc = 0; kc < 8; kc++) {
        // stage A chunks (64 x 16) for both matrices, converted to tf32
        {
            int node = n0 + arow;
            float4 va = make_float4(0.f, 0.f, 0.f, 0.f), vf = va;
            if (node < N) {
                va = *(const float4*)(agg  + (size_t)node * FD + kc * 16 + aj * 4);
                vf = *(const float4*)(feat + (size_t)node * FD + kc * 16 + aj * 4);
            }
            float av[4] = {va.x, va.y, va.z, va.w};
            float fv[4] = {vf.x, vf.y, vf.z, vf.w};
#pragma unroll
            for (int i = 0; i < 4; i++) {
                unsigned ab, fb;
                asm("cvt.rna.tf32.f32 %0, %1;" : "=r"(ab) : "f"(av[i]));
                asm("cvt.rna.tf32.f32 %0, %1;" : "=r"(fb) : "f"(fv[i]));
                sA[arow][aj * 4 + i] = __uint_as_float(ab);
                sF[arow][aj * 4 + i] = __uint_as_float(fb);
            }
        }
        // stage B chunks (16 x 256) for both weight matrices
#pragma unroll
        for (int j = 0; j < 16; j++) {
            int idx = t + j * 256;
            int k = idx >> 8, n = idx & 255;
            sW[k][n] = __uint_as_float(Wt0[(kc * 16 + k) * HD + n]);
            sS[k][n] = __uint_as_float(Wt1[(kc * 16 + k) * HD + n]);
        }
        __syncthreads();

#pragma unroll
        for (int s = 0; s < 2; s++) {
            int kk = s * 8 + (lane & 3);
            int r0 = wy * 16 + (lane >> 2);
            unsigned aG0 = __float_as_uint(sA[r0][kk]);
            unsigned aG1 = __float_as_uint(sA[r0 + 8][kk]);
            unsigned aG2 = __float_as_uint(sA[r0][kk + 4]);
            unsigned aG3 = __float_as_uint(sA[r0 + 8][kk + 4]);
            unsigned aF0 = __float_as_uint(sF[r0][kk]);
            unsigned aF1 = __float_as_uint(sF[r0 + 8][kk]);
            unsigned aF2 = __float_as_uint(sF[r0][kk + 4]);
            unsigned aF3 = __float_as_uint(sF[r0 + 8][kk + 4]);
#pragma unroll
            for (int ni = 0; ni < 16; ni++) {
                int n = wx * 128 + ni * 8 + (lane >> 2);
                unsigned w0 = __float_as_uint(sW[kk][n]);
                unsigned w1 = __float_as_uint(sW[kk + 4][n]);
                mma_tf32(accG[ni], aG0, aG1, aG2, aG3, w0, w1);
                unsigned s0 = __float_as_uint(sS[kk][n]);
                unsigned s1 = __float_as_uint(sS[kk + 4][n]);
                mma_tf32(accS[ni], aF0, aF1, aF2, aF3, s0, s1);
            }
        }
        __syncthreads();
    }

    // ---- epilogue ----
    int r0 = wy * 16 + (lane >> 2);
    int colb = wx * 128 + 2 * (lane & 3);

#pragma unroll
    for (int ni = 0; ni < 16; ni++) {
        float2 bb = *(const float2*)(bias + colb + ni * 8);
        float2 sb = *(const float2*)(sbias + colb + ni * 8);
        accG[ni][0] += bb.x; accG[ni][1] += bb.y;
        accG[ni][2] += bb.x; accG[ni][3] += bb.y;
        accS[ni][0] += sb.x; accS[ni][1] += sb.y;
        accS[ni][2] += sb.x; accS[ni][3] += sb.y;
    }

    // LN row statistics over accG
    float s1 = 0.f, q1 = 0.f, s2 = 0.f, q2 = 0.f;
#pragma unroll
    for (int ni = 0; ni < 16; ni++) {
        s1 += accG[ni][0] + accG[ni][1];
        q1 += accG[ni][0] * accG[ni][0] + accG[ni][1] * accG[ni][1];
        s2 += accG[ni][2] + accG[ni][3];
        q2 += accG[ni][2] * accG[ni][2] + accG[ni][3] * accG[ni][3];
    }
#pragma unroll
    for (int off = 1; off <= 2; off <<= 1) {
        s1 += __shfl_xor_sync(0xffffffffu, s1, off);
        q1 += __shfl_xor_sync(0xffffffffu, q1, off);
        s2 += __shfl_xor_sync(0xffffffffu, s2, off);
        q2 += __shfl_xor_sync(0xffffffffu, q2, off);
    }
    if ((lane & 3) == 0) {
        sLN[r0][wx] = make_float2(s1, q1);
        sLN[r0 + 8][wx] = make_float2(s2, q2);
    }
    __syncthreads();
    float2 pa = sLN[r0][0], pb = sLN[r0][1];
    float mu1 = (pa.x + pb.x) * (1.0f / HD);
    float var1 = (pa.y + pb.y) * (1.0f / HD) - mu1 * mu1;
    float inv1 = rsqrtf(var1 + 1e-5f);
    float2 pc = sLN[r0 + 8][0], pd = sLN[r0 + 8][1];
    float mu2 = (pc.x + pd.x) * (1.0f / HD);
    float var2 = (pc.y + pd.y) * (1.0f / HD) - mu2 * mu2;
    float inv2 = rsqrtf(var2 + 1e-5f);

    int node1 = n0 + r0, node2 = n0 + r0 + 8;
#pragma unroll
    for (int ni = 0; ni < 16; ni++) {
        int col = colb + ni * 8;
        float2 gm = *(const float2*)(gamma + col);
        float2 bt = *(const float2*)(beta + col);
        if (node1 < N) {
            float2 o;
            o.x = fmaxf((accG[ni][0] - mu1) * inv1 * gm.x + bt.x, 0.f) + accS[ni][0];
            o.y = fmaxf((accG[ni][1] - mu1) * inv1 * gm.y + bt.y, 0.f) + accS[ni][1];
            *(float2*)(out + (size_t)node1 * HD + col) = o;
        }
        if (node2 < N) {
            float2 o;
            o.x = fmaxf((accG[ni][2] - mu2) * inv2 * gm.x + bt.x, 0.f) + accS[ni][2];
            o.y = fmaxf((accG[ni][3] - mu2) * inv2 * gm.y + bt.y, 0.f) + accS[ni][3];
            *(float2*)(out + (size_t)node2 * HD + col) = o;
        }
    }
}

// ---------------------------------------------------------------------------
extern "C" void kernel_launch(void* const* d_in, const int* in_sizes, int n_in,
                              void* d_out, int out_size)
{
    const float* feat = (const float*)d_in[0];
    const void*  src  = d_in[1];
    const void*  dst  = d_in[2];
    const float* Wm   = (const float*)d_in[3];
    const float* bv   = (const float*)d_in[4];
    const float* gm   = (const float*)d_in[5];
    const float* bt   = (const float*)d_in[6];
    const float* sWm  = (const float*)d_in[7];
    const float* sbv  = (const float*)d_in[8];
    float* out = (float*)d_out;

    int N = in_sizes[0] / FD;
    int E = in_sizes[1];
    int nb = (N + 1023) / 1024;

    k_init<<<(N + 255) / 256, 256>>>((const int*)src, E, N);
    k_count<<<(E / 2 + 255) / 256, 256>>>(src, dst, E);
    k_scan1<<<nb, 1024>>>(N);
    k_scan2<<<1, 128>>>(nb);
    k_scan3<<<nb, 1024>>>(N, E);
    k_fill<<<(E + 255) / 256, 256>>>(src, dst, E);
    k_gather<<<(N * 32 + 255) / 256, 256>>>(feat, N);
    k_prep<<<(FD * HD + 255) / 256, 256>>>(Wm, sWm);

    float* aggp = nullptr;
    cudaGetSymbolAddress((void**)&aggp, g_agg);
    unsigned* wt0 = nullptr;
    cudaGetSymbolAddress((void**)&wt0, g_Wt0);
    unsigned* wt1 = nullptr;
    cudaGetSymbolAddress((void**)&wt1, g_Wt1);

    k_fused<<<(N + 63) / 64, 256>>>(feat, aggp, wt0, wt1, bv, gm, bt, sbv, out, N);
}

// round 7
// speedup vs baseline: 2.5969x; 1.3333x over previous
#include <cuda_runtime.h>
#include <cuda_fp16.h>
#include <stdint.h>

#define NN 100000
#define EMAX 1700000
#define FD 128
#define HD 256

// ---------------- scratch (__device__ globals; no allocs allowed) ----------
__device__ int    g_deg_out[NN];
__device__ int    g_deg_in[NN];
__device__ int    g_is64;
__device__ float  g_nsrc[NN];
__device__ float  g_ndst[NN];
__device__ int    g_rowptr[NN + 1];
__device__ int    g_cursor[NN];
__device__ int    g_bsum[128];
__device__ int    g_eidx[EMAX];
__device__ float  g_agg[(size_t)NN * FD];
__device__ __half g_h16[(size_t)NN * FD];
// weights as tf32-bit pairs (k, k+4): index [(kc*8+p)*256 + n]
__device__ float2 g_Wp0[64 * 256];
__device__ float2 g_Wp1[64 * 256];

// ---------------------------------------------------------------------------
__global__ void k_init(const int* __restrict__ srcw, int E, int N) {
    int i = blockIdx.x * blockDim.x + threadIdx.x;
    if (i < N) { g_deg_out[i] = 0; g_deg_in[i] = 0; }
    if (blockIdx.x == 0) {
        __shared__ int bad;
        if (threadIdx.x == 0) bad = 0;
        __syncthreads();
        int n = E / 2; if (n > 256) n = 256;
        if ((int)threadIdx.x < n && srcw[2 * threadIdx.x + 1] != 0) bad = 1;
        __syncthreads();
        if (threadIdx.x == 0) g_is64 = (bad == 0);
    }
}

__device__ __forceinline__ int load_idx(const void* p, int i) {
    if (g_is64) return (int)((const long long*)p)[i];
    return ((const int*)p)[i];
}

__global__ void k_count(const void* __restrict__ src, const void* __restrict__ dst, int E) {
    int i = (blockIdx.x * blockDim.x + threadIdx.x) * 2;
    if (i < E) {
        atomicAdd(&g_deg_out[load_idx(src, i)], 1);
        atomicAdd(&g_deg_in[load_idx(dst, i)], 1);
        if (i + 1 < E) {
            atomicAdd(&g_deg_out[load_idx(src, i + 1)], 1);
            atomicAdd(&g_deg_in[load_idx(dst, i + 1)], 1);
        }
    }
}

// scan phase 1 (also computes both norms)
__global__ void k_scan1(int N) {
    __shared__ int s[1024];
    int tid = threadIdx.x;
    int i = blockIdx.x * 1024 + tid;
    int v = 0;
    if (i < N) {
        int din = g_deg_in[i];
        v = din;
        g_nsrc[i] = rsqrtf(fmaxf((float)g_deg_out[i], 1.0f));
        g_ndst[i] = rsqrtf(fmaxf((float)din, 1.0f));
    }
    s[tid] = v;
    for (int off = 1; off < 1024; off <<= 1) {
        __syncthreads();
        int t = (tid >= off) ? s[tid - off] : 0;
        __syncthreads();
        s[tid] += t;
    }
    __syncthreads();
    if (i < N) g_rowptr[i] = s[tid] - v;
    if (tid == 1023) g_bsum[blockIdx.x] = s[1023];
}

// scan phase 2+3 merged: each block sums block-sums below it itself
__global__ void k_scan3(int N, int E) {
    __shared__ int ssum;
    int tid = threadIdx.x;
    if (tid == 0) ssum = 0;
    __syncthreads();
    if (tid < blockIdx.x) atomicAdd(&ssum, g_bsum[tid]);
    __syncthreads();
    int i = blockIdx.x * 1024 + tid;
    if (i < N) {
        int val = g_rowptr[i] + ssum;
        g_rowptr[i] = val;
        g_cursor[i] = val;
    }
    if (i == 0) g_rowptr[N] = E;
}

// h16 = fp16(feat * norm_src); one thread per 16 elements
__global__ void k_h16(const float* __restrict__ feat, int N) {
    int i = blockIdx.x * blockDim.x + threadIdx.x;
    if (i >= N * 8) return;
    int node = i >> 3, seg = i & 7;
    float ns = g_nsrc[node];
    const float4* fp = (const float4*)(feat + (size_t)node * FD + seg * 16);
    __half2 o[8];
#pragma unroll
    for (int j = 0; j < 4; j++) {
        float4 v = fp[j];
        o[j * 2]     = __floats2half2_rn(v.x * ns, v.y * ns);
        o[j * 2 + 1] = __floats2half2_rn(v.z * ns, v.w * ns);
    }
    __half* hp = g_h16 + (size_t)node * FD + seg * 16;
    *(uint4*)hp       = *(uint4*)&o[0];
    *(uint4*)(hp + 8) = *(uint4*)&o[4];
}

__global__ void k_fill(const void* __restrict__ src, const void* __restrict__ dst, int E) {
    int i = blockIdx.x * blockDim.x + threadIdx.x;
    if (i < E) {
        int d = load_idx(dst, i);
        int pos = atomicAdd(&g_cursor[d], 1);
        g_eidx[pos] = load_idx(src, i);
    }
}

// warp per node: agg[n] = norm_dst[n] * sum_{e in CSR(n)} h16[src_e]
__global__ void k_gather(int N) {
    int w = (blockIdx.x * blockDim.x + threadIdx.x) >> 5;
    int lane = threadIdx.x & 31;
    if (w >= N) return;
    int beg = g_rowptr[w], end = g_rowptr[w + 1];
    float4 acc = make_float4(0.f, 0.f, 0.f, 0.f);
    for (int base = beg; base < end; base += 32) {
        int idx = base + lane;
        int mye = (idx < end) ? g_eidx[idx] : 0;
        int cnt = min(32, end - base);
        for (int i = 0; i < cnt; i++) {
            int s = __shfl_sync(0xffffffffu, mye, i);
            uint2 hv = *(const uint2*)(g_h16 + (size_t)s * FD + (lane << 2));
            float2 f0 = __half22float2(*(__half2*)&hv.x);
            float2 f1 = __half22float2(*(__half2*)&hv.y);
            acc.x += f0.x; acc.y += f0.y; acc.z += f1.x; acc.w += f1.y;
        }
    }
    float nd = g_ndst[w];
    acc.x *= nd; acc.y *= nd; acc.z *= nd; acc.w *= nd;
    ((float4*)g_agg)[(size_t)w * 32 + lane] = acc;
}

// build paired tf32 weights: pair (k, k+4) within each 16-wide kc chunk
__global__ void k_prep(const float* __restrict__ W, const float* __restrict__ sW) {
    int i = blockIdx.x * blockDim.x + threadIdx.x;  // 0..16383
    if (i >= 64 * 256) return;
    int pp = i >> 8, n = i & 255;
    int kc = pp >> 3, p = pp & 7;
    int krow = kc * 16 + ((p >> 2) << 3) + (p & 3);
    unsigned a0, a1, b0, b1;
    asm("cvt.rna.tf32.f32 %0, %1;" : "=r"(a0) : "f"(W[krow * HD + n]));
    asm("cvt.rna.tf32.f32 %0, %1;" : "=r"(a1) : "f"(W[(krow + 4) * HD + n]));
    asm("cvt.rna.tf32.f32 %0, %1;" : "=r"(b0) : "f"(sW[krow * HD + n]));
    asm("cvt.rna.tf32.f32 %0, %1;" : "=r"(b1) : "f"(sW[(krow + 4) * HD + n]));
    g_Wp0[i] = make_float2(__uint_as_float(a0), __uint_as_float(a1));
    g_Wp1[i] = make_float2(__uint_as_float(b0), __uint_as_float(b1));
}

// ---------------------------------------------------------------------------
__device__ __forceinline__ void mma_tf32(float* c, unsigned a0, unsigned a1,
                                         unsigned a2, unsigned a3,
                                         unsigned b0, unsigned b1) {
    asm volatile(
        "mma.sync.aligned.m16n8k8.row.col.f32.tf32.tf32.f32 "
        "{%0,%1,%2,%3}, {%4,%5,%6,%7}, {%8,%9}, {%0,%1,%2,%3};"
        : "+f"(c[0]), "+f"(c[1]), "+f"(c[2]), "+f"(c[3])
        : "r"(a0), "r"(a1), "r"(a2), "r"(a3), "r"(b0), "r"(b1));
}

static __device__ __forceinline__ uint32_t smem_u32(const void* p) {
    uint32_t a;
    asm("{ .reg .u64 t; cvta.to.shared.u64 t, %1; cvt.u32.u64 %0, t; }"
        : "=r"(a) : "l"(p));
    return a;
}

// dynamic smem layout (bytes); A raw fp32 [64][20], B pairs [8][260] float2
#define AGO(b) ((b) ? 5120 : 0)
#define AFO(b) ((b) ? 15360 : 10240)
#define BWO(b) ((b) ? 37120 : 20480)
#define BSO(b) ((b) ? 70400 : 53760)
#define SMTOT  87040

__device__ __forceinline__ void stage(char* sm, uint32_t sb, int b, int kc,
                                      const float* agg, const float* feat,
                                      int n0, int N, int t)
{
    int row = t >> 2, c4 = t & 3;
    int node = n0 + row;
    int sz = (node < N) ? 16 : 0;
    uint32_t dA = sb + AGO(b) + (row * 20 + c4 * 4) * 4;
    const float* sA = agg + (size_t)node * FD + kc * 16 + c4 * 4;
    asm volatile("cp.async.cg.shared.global [%0], [%1], 16, %2;"
                 :: "r"(dA), "l"(sA), "r"(sz));
    uint32_t dF = sb + AFO(b) + (row * 20 + c4 * 4) * 4;
    const float* sF = feat + (size_t)node * FD + kc * 16 + c4 * 4;
    asm volatile("cp.async.cg.shared.global [%0], [%1], 16, %2;"
                 :: "r"(dF), "l"(sF), "r"(sz));
#pragma unroll
    for (int j = 0; j < 8; j++) {
        int idx = t + (j << 8);
        int p = idx >> 8, n = idx & 255;
        uint32_t dW = sb + BWO(b) + (p * 260 + n) * 8;
        const float2* srcW = g_Wp0 + (kc * 8 + p) * 256 + n;
        asm volatile("cp.async.ca.shared.global [%0], [%1], 8;"
                     :: "r"(dW), "l"(srcW));
        uint32_t dS = sb + BSO(b) + (p * 260 + n) * 8;
        const float2* srcS = g_Wp1 + (kc * 8 + p) * 256 + n;
        asm volatile("cp.async.ca.shared.global [%0], [%1], 8;"
                     :: "r"(dS), "l"(srcS));
    }
    asm volatile("cp.async.commit_group;");
}

__global__ __launch_bounds__(256)
void k_fused(const float* __restrict__ feat, const float* __restrict__ agg,
             const float* __restrict__ bias, const float* __restrict__ gamma,
             const float* __restrict__ beta, const float* __restrict__ sbias,
             float* __restrict__ out, int N)
{
    extern __shared__ char sm[];
    uint32_t sb = smem_u32(sm);
    int t = threadIdx.x;
    int lane = t & 31, wid = t >> 5;
    int wy = wid >> 1, wx = wid & 1;
    int n0 = blockIdx.x * 64;

    float accG[16][4], accS[16][4];
#pragma unroll
    for (int i = 0; i < 16; i++)
#pragma unroll
        for (int j = 0; j < 4; j++) { accG[i][j] = 0.f; accS[i][j] = 0.f; }

    stage(sm, sb, 0, 0, agg, feat, n0, N, t);

    for (int kc = 0; kc < 8; kc++) {
        int b = kc & 1;
        if (kc + 1 < 8) {
            stage(sm, sb, b ^ 1, kc + 1, agg, feat, n0, N, t);
            asm volatile("cp.async.wait_group 1;");
        } else {
            asm volatile("cp.async.wait_group 0;");
        }
        __syncthreads();

        const float* sAg = (const float*)(sm + AGO(b));
        const float* sAf = (const float*)(sm + AFO(b));
        const float2* sBw = (const float2*)(sm + BWO(b));
        const float2* sBs = (const float2*)(sm + BSO(b));

#pragma unroll
        for (int s = 0; s < 2; s++) {
            int kk = s * 8 + (lane & 3);
            int r0 = wy * 16 + (lane >> 2);
            unsigned aG0, aG1, aG2, aG3, aF0, aF1, aF2, aF3;
            asm("cvt.rna.tf32.f32 %0, %1;" : "=r"(aG0) : "f"(sAg[r0 * 20 + kk]));
            asm("cvt.rna.tf32.f32 %0, %1;" : "=r"(aG1) : "f"(sAg[(r0 + 8) * 20 + kk]));
            asm("cvt.rna.tf32.f32 %0, %1;" : "=r"(aG2) : "f"(sAg[r0 * 20 + kk + 4]));
            asm("cvt.rna.tf32.f32 %0, %1;" : "=r"(aG3) : "f"(sAg[(r0 + 8) * 20 + kk + 4]));
            asm("cvt.rna.tf32.f32 %0, %1;" : "=r"(aF0) : "f"(sAf[r0 * 20 + kk]));
            asm("cvt.rna.tf32.f32 %0, %1;" : "=r"(aF1) : "f"(sAf[(r0 + 8) * 20 + kk]));
            asm("cvt.rna.tf32.f32 %0, %1;" : "=r"(aF2) : "f"(sAf[r0 * 20 + kk + 4]));
            asm("cvt.rna.tf32.f32 %0, %1;" : "=r"(aF3) : "f"(sAf[(r0 + 8) * 20 + kk + 4]));
            int p0 = s * 4 + (lane & 3);
#pragma unroll
            for (int ni = 0; ni < 16; ni++) {
                int n = wx * 128 + ni * 8 + (lane >> 2);
                float2 wv = sBw[p0 * 260 + n];
                mma_tf32(accG[ni], aG0, aG1, aG2, aG3,
                         __float_as_uint(wv.x), __float_as_uint(wv.y));
                float2 sv = sBs[p0 * 260 + n];
                mma_tf32(accS[ni], aF0, aF1, aF2, aF3,
                         __float_as_uint(sv.x), __float_as_uint(sv.y));
            }
        }
        __syncthreads();
    }

    // ---- epilogue ----
    float2* sLN = (float2*)sm;          // [64][2]; staging smem is dead
    int r0 = wy * 16 + (lane >> 2);
    int colb = wx * 128 + 2 * (lane & 3);

#pragma unroll
    for (int ni = 0; ni < 16; ni++) {
        float2 bb = *(const float2*)(bias + colb + ni * 8);
        float2 sbv = *(const float2*)(sbias + colb + ni * 8);
        accG[ni][0] += bb.x; accG[ni][1] += bb.y;
        accG[ni][2] += bb.x; accG[ni][3] += bb.y;
        accS[ni][0] += sbv.x; accS[ni][1] += sbv.y;
        accS[ni][2] += sbv.x; accS[ni][3] += sbv.y;
    }

    float s1 = 0.f, q1 = 0.f, s2 = 0.f, q2 = 0.f;
#pragma unroll
    for (int ni = 0; ni < 16; ni++) {
        s1 += accG[ni][0] + accG[ni][1];
        q1 += accG[ni][0] * accG[ni][0] + accG[ni][1] * accG[ni][1];
        s2 += accG[ni][2] + accG[ni][3];
        q2 += accG[ni][2] * accG[ni][2] + accG[ni][3] * accG[ni][3];
    }
#pragma unroll
    for (int off = 1; off <= 2; off <<= 1) {
        s1 += __shfl_xor_sync(0xffffffffu, s1, off);
        q1 += __shfl_xor_sync(0xffffffffu, q1, off);
        s2 += __shfl_xor_sync(0xffffffffu, s2, off);
        q2 += __shfl_xor_sync(0xffffffffu, q2, off);
    }
    if ((lane & 3) == 0) {
        sLN[r0 * 2 + wx] = make_float2(s1, q1);
        sLN[(r0 + 8) * 2 + wx] = make_float2(s2, q2);
    }
    __syncthreads();
    float2 pa = sLN[r0 * 2 + 0], pb = sLN[r0 * 2 + 1];
    float mu1 = (pa.x + pb.x) * (1.0f / HD);
    float var1 = (pa.y + pb.y) * (1.0f / HD) - mu1 * mu1;
    float inv1 = rsqrtf(var1 + 1e-5f);
    float2 pc = sLN[(r0 + 8) * 2 + 0], pd = sLN[(r0 + 8) * 2 + 1];
    float mu2 = (pc.x + pd.x) * (1.0f / HD);
    float var2 = (pc.y + pd.y) * (1.0f / HD) - mu2 * mu2;
    float inv2 = rsqrtf(var2 + 1e-5f);

    int node1 = n0 + r0, node2 = n0 + r0 + 8;
#pragma unroll
    for (int ni = 0; ni < 16; ni++) {
        int col = colb + ni * 8;
        float2 gm = *(const float2*)(gamma + col);
        float2 bt = *(const float2*)(beta + col);
        if (node1 < N) {
            float2 o;
            o.x = fmaxf((accG[ni][0] - mu1) * inv1 * gm.x + bt.x, 0.f) + accS[ni][0];
            o.y = fmaxf((accG[ni][1] - mu1) * inv1 * gm.y + bt.y, 0.f) + accS[ni][1];
            *(float2*)(out + (size_t)node1 * HD + col) = o;
        }
        if (node2 < N) {
            float2 o;
            o.x = fmaxf((accG[ni][2] - mu2) * inv2 * gm.x + bt.x, 0.f) + accS[ni][2];
            o.y = fmaxf((accG[ni][3] - mu2) * inv2 * gm.y + bt.y, 0.f) + accS[ni][3];
            *(float2*)(out + (size_t)node2 * HD + col) = o;
        }
    }
}

// ---------------------------------------------------------------------------
extern "C" void kernel_launch(void* const* d_in, const int* in_sizes, int n_in,
                              void* d_out, int out_size)
{
    const float* feat = (const float*)d_in[0];
    const void*  src  = d_in[1];
    const void*  dst  = d_in[2];
    const float* Wm   = (const float*)d_in[3];
    const float* bv   = (const float*)d_in[4];
    const float* gm   = (const float*)d_in[5];
    const float* bt   = (const float*)d_in[6];
    const float* sWm  = (const float*)d_in[7];
    const float* sbv  = (const float*)d_in[8];
    float* out = (float*)d_out;

    int N = in_sizes[0] / FD;
    int E = in_sizes[1];
    int nb = (N + 1023) / 1024;

    k_init<<<(N + 255) / 256, 256>>>((const int*)src, E, N);
    k_count<<<(E / 2 + 255) / 256, 256>>>(src, dst, E);
    k_scan1<<<nb, 1024>>>(N);
    k_scan3<<<nb, 1024>>>(N, E);
    k_h16<<<(N * 8 + 255) / 256, 256>>>(feat, N);
    k_fill<<<(E + 255) / 256, 256>>>(src, dst, E);
    k_gather<<<(N * 32 + 255) / 256, 256>>>(N);
    k_prep<<<(64 * 256 + 255) / 256, 256>>>(Wm, sWm);

    float* aggp = nullptr;
    cudaGetSymbolAddress((void**)&aggp, g_agg);

    cudaFuncSetAttribute(k_fused, cudaFuncAttributeMaxDynamicSharedMemorySize, SMTOT);
    k_fused<<<(N + 63) / 64, 256, SMTOT>>>(feat, aggp, bv, gm, bt, sbv, out, N);
}

// round 9
// speedup vs baseline: 3.3168x; 1.2772x over previous
#include <cuda_runtime.h>
#include <cuda_fp16.h>
#include <stdint.h>

#define NN 100000
#define EMAX 1700000
#define FD 128
#define HD 256

// ---------------- scratch (__device__ globals; no allocs allowed) ----------
__device__ int    g_deg_out[NN];
__device__ int    g_deg_in[NN];
__device__ int    g_is64;
__device__ float  g_nsrc[NN];
__device__ float  g_ndst[NN];
__device__ int    g_rowptr[NN + 1];
__device__ int    g_cursor[NN];
__device__ int    g_bsum[128];
__device__ int    g_eidx[EMAX];
__device__ __half g_h16[(size_t)NN * FD];   // feat * norm_src (fp16), for gather
__device__ __half g_a16[(size_t)NN * FD];   // agg (fp16), A of GCN gemm
__device__ __half g_f16[(size_t)NN * FD];   // raw feat (fp16), A of skip gemm
// B packed for m16n8k16: [(kc*4+p0)*256 + n] -> uint2{half2(k0,k0+1), half2(k0+8,k0+9)}
__device__ uint2  g_W16[32 * 256];
__device__ uint2  g_S16[32 * 256];

// ---------------------------------------------------------------------------
__global__ void k_init(const int* __restrict__ srcw, int E, int N) {
    int i = blockIdx.x * blockDim.x + threadIdx.x;
    if (i < N) { g_deg_out[i] = 0; g_deg_in[i] = 0; }
    if (blockIdx.x == 0) {
        __shared__ int bad;
        if (threadIdx.x == 0) bad = 0;
        __syncthreads();
        int n = E / 2; if (n > 256) n = 256;
        if ((int)threadIdx.x < n && srcw[2 * threadIdx.x + 1] != 0) bad = 1;
        __syncthreads();
        if (threadIdx.x == 0) g_is64 = (bad == 0);
    }
}

__device__ __forceinline__ int load_idx(const void* p, int i) {
    if (g_is64) return (int)((const long long*)p)[i];
    return ((const int*)p)[i];
}

__global__ void k_count(const void* __restrict__ src, const void* __restrict__ dst, int E) {
    int i = (blockIdx.x * blockDim.x + threadIdx.x) * 2;
    if (i < E) {
        atomicAdd(&g_deg_out[load_idx(src, i)], 1);
        atomicAdd(&g_deg_in[load_idx(dst, i)], 1);
        if (i + 1 < E) {
            atomicAdd(&g_deg_out[load_idx(src, i + 1)], 1);
            atomicAdd(&g_deg_in[load_idx(dst, i + 1)], 1);
        }
    }
}

__global__ void k_scan1(int N) {
    __shared__ int s[1024];
    int tid = threadIdx.x;
    int i = blockIdx.x * 1024 + tid;
    int v = 0;
    if (i < N) {
        int din = g_deg_in[i];
        v = din;
        g_nsrc[i] = rsqrtf(fmaxf((float)g_deg_out[i], 1.0f));
        g_ndst[i] = rsqrtf(fmaxf((float)din, 1.0f));
    }
    s[tid] = v;
    for (int off = 1; off < 1024; off <<= 1) {
        __syncthreads();
        int t = (tid >= off) ? s[tid - off] : 0;
        __syncthreads();
        s[tid] += t;
    }
    __syncthreads();
    if (i < N) g_rowptr[i] = s[tid] - v;
    if (tid == 1023) g_bsum[blockIdx.x] = s[1023];
}

__global__ void k_scan3(int N, int E) {
    __shared__ int ssum;
    int tid = threadIdx.x;
    if (tid == 0) ssum = 0;
    __syncthreads();
    if (tid < blockIdx.x) atomicAdd(&ssum, g_bsum[tid]);
    __syncthreads();
    int i = blockIdx.x * 1024 + tid;
    if (i < N) {
        int val = g_rowptr[i] + ssum;
        g_rowptr[i] = val;
        g_cursor[i] = val;
    }
    if (i == 0) g_rowptr[N] = E;
}

// h16 = fp16(feat * norm_src), f16 = fp16(feat); one thread per 16 elements
__global__ void k_h16(const float* __restrict__ feat, int N) {
    int i = blockIdx.x * blockDim.x + threadIdx.x;
    if (i >= N * 8) return;
    int node = i >> 3, seg = i & 7;
    float ns = g_nsrc[node];
    const float4* fp = (const float4*)(feat + (size_t)node * FD + seg * 16);
    __half2 o[8], f[8];
#pragma unroll
    for (int j = 0; j < 4; j++) {
        float4 v = fp[j];
        o[j * 2]     = __floats2half2_rn(v.x * ns, v.y * ns);
        o[j * 2 + 1] = __floats2half2_rn(v.z * ns, v.w * ns);
        f[j * 2]     = __floats2half2_rn(v.x, v.y);
        f[j * 2 + 1] = __floats2half2_rn(v.z, v.w);
    }
    size_t off = (size_t)node * FD + seg * 16;
    *(uint4*)(g_h16 + off)     = *(uint4*)&o[0];
    *(uint4*)(g_h16 + off + 8) = *(uint4*)&o[4];
    *(uint4*)(g_f16 + off)     = *(uint4*)&f[0];
    *(uint4*)(g_f16 + off + 8) = *(uint4*)&f[4];
}

__global__ void k_fill(const void* __restrict__ src, const void* __restrict__ dst, int E) {
    int i = blockIdx.x * blockDim.x + threadIdx.x;
    if (i < E) {
        int d = load_idx(dst, i);
        int pos = atomicAdd(&g_cursor[d], 1);
        g_eidx[pos] = load_idx(src, i);
    }
}

// warp per node: a16[n] = fp16(norm_dst[n] * sum h16[src_e])
__global__ void k_gather(int N) {
    int w = (blockIdx.x * blockDim.x + threadIdx.x) >> 5;
    int lane = threadIdx.x & 31;
    if (w >= N) return;
    int beg = g_rowptr[w], end = g_rowptr[w + 1];
    float4 acc = make_float4(0.f, 0.f, 0.f, 0.f);
    for (int base = beg; base < end; base += 32) {
        int idx = base + lane;
        int mye = (idx < end) ? g_eidx[idx] : 0;
        int cnt = min(32, end - base);
        for (int i = 0; i < cnt; i++) {
            int s = __shfl_sync(0xffffffffu, mye, i);
            uint2 hv = *(const uint2*)(g_h16 + (size_t)s * FD + (lane << 2));
            float2 f0 = __half22float2(*(__half2*)&hv.x);
            float2 f1 = __half22float2(*(__half2*)&hv.y);
            acc.x += f0.x; acc.y += f0.y; acc.z += f1.x; acc.w += f1.y;
        }
    }
    float nd = g_ndst[w];
    __half2 o0 = __floats2half2_rn(acc.x * nd, acc.y * nd);
    __half2 o1 = __floats2half2_rn(acc.z * nd, acc.w * nd);
    uint2 ov = make_uint2(*(unsigned*)&o0, *(unsigned*)&o1);
    *(uint2*)(g_a16 + (size_t)w * FD + (lane << 2)) = ov;
}

// pack weights fp16 for m16n8k16 B fragments
__global__ void k_prep(const float* __restrict__ W, const float* __restrict__ sW) {
    int i = blockIdx.x * blockDim.x + threadIdx.x;  // 0..8191
    if (i >= 32 * 256) return;
    int kc = i >> 10, p0 = (i >> 8) & 3, n = i & 255;
    int k0 = kc * 16 + p0 * 2;
    __half2 w0 = __floats2half2_rn(W[k0 * HD + n],       W[(k0 + 1) * HD + n]);
    __half2 w1 = __floats2half2_rn(W[(k0 + 8) * HD + n], W[(k0 + 9) * HD + n]);
    g_W16[i] = make_uint2(*(unsigned*)&w0, *(unsigned*)&w1);
    __half2 s0 = __floats2half2_rn(sW[k0 * HD + n],       sW[(k0 + 1) * HD + n]);
    __half2 s1 = __floats2half2_rn(sW[(k0 + 8) * HD + n], sW[(k0 + 9) * HD + n]);
    g_S16[i] = make_uint2(*(unsigned*)&s0, *(unsigned*)&s1);
}

// ---------------------------------------------------------------------------
__device__ __forceinline__ void mma_f16(float* c, unsigned a0, unsigned a1,
                                        unsigned a2, unsigned a3,
                                        unsigned b0, unsigned b1) {
    asm volatile(
        "mma.sync.aligned.m16n8k16.row.col.f32.f16.f16.f32 "
        "{%0,%1,%2,%3}, {%4,%5,%6,%7}, {%8,%9}, {%0,%1,%2,%3};"
        : "+f"(c[0]), "+f"(c[1]), "+f"(c[2]), "+f"(c[3])
        : "r"(a0), "r"(a1), "r"(a2), "r"(a3), "r"(b0), "r"(b1));
}

static __device__ __forceinline__ uint32_t smem_u32(const void* p) {
    uint32_t a;
    asm("{ .reg .u64 t; cvta.to.shared.u64 t, %1; cvt.u32.u64 %0, t; }"
        : "=r"(a) : "l"(p));
    return a;
}

// smem layout per buffer (bytes):
//  A_agg [32 rows][24 halves] = 1536 ; A_feat 1536
//  B_w   [4 rows][260 uint2]  = 8320 ; B_s    8320      -> 19712 per buffer
#define ABYTES   1536
#define BBYTES   8320
#define BUF(b)   ((b) * 19712)
#define AGO(b)   (BUF(b))
#define AFO(b)   (BUF(b) + ABYTES)
#define BWO(b)   (BUF(b) + 2 * ABYTES)
#define BSO(b)   (BUF(b) + 2 * ABYTES + BBYTES)
#define SMTOT    39424

// Stage kc chunk into buffer b: 1152 16B chunks (1024 B, 128 A)
__device__ __forceinline__ void stage(uint32_t sb, int b, int kc,
                                      int n0, int N, int t)
{
#pragma unroll
    for (int j = 0; j < 5; j++) {
        int c = t + (j << 8);
        if (c < 1024) {                       // B chunks
            int m = c >> 9, r = (c >> 7) & 3, col = (c & 127) * 2;  // uint2 idx
            const uint2* srcp = (m ? g_S16 : g_W16) + (kc * 4 + r) * 256 + col;
            uint32_t dst = sb + (m ? BSO(b) : BWO(b)) + r * 2080 + col * 8;
            asm volatile("cp.async.ca.shared.global [%0], [%1], 16;"
                         :: "r"(dst), "l"(srcp));
        } else if (c < 1152) {                // A chunks
            int c2 = c - 1024;
            int m = c2 >> 6, row = (c2 >> 1) & 31, seg = c2 & 1;
            int node = n0 + row;
            int sz = (node < N) ? 16 : 0;
            const __half* srcp = (m ? g_f16 : g_a16) +
                                 (size_t)node * FD + kc * 16 + seg * 8;
            uint32_t dst = sb + (m ? AFO(b) : AGO(b)) + row * 48 + seg * 16;
            asm volatile("cp.async.cg.shared.global [%0], [%1], 16, %2;"
                         :: "r"(dst), "l"(srcp), "r"(sz));
        }
    }
    asm volatile("cp.async.commit_group;");
}

// Fused dual-GEMM + LN + ReLU + skip-add.
// Block tile 32 rows x 256 cols; 8 warps = 2 row-groups x 4 col-groups;
// warp tile 16x64 per matrix (ni=8). fp16 m16n8k16, fp32 accum. occ=2.
__global__ __launch_bounds__(256, 2)
void k_fused(const float* __restrict__ bias, const float* __restrict__ gamma,
             const float* __restrict__ beta, const float* __restrict__ sbias,
             float* __restrict__ out, int N)
{
    extern __shared__ char sm[];
    uint32_t sb = smem_u32(sm);
    int t = threadIdx.x;
    int lane = t & 31, wid = t >> 5;
    int wy = wid >> 2, wx = wid & 3;      // wy 0..1, wx 0..3
    int n0 = blockIdx.x * 32;

    float accG[8][4], accS[8][4];
#pragma unroll
    for (int i = 0; i < 8; i++)
#pragma unroll
        for (int j = 0; j < 4; j++) { accG[i][j] = 0.f; accS[i][j] = 0.f; }

    stage(sb, 0, 0, n0, N, t);

    int r0 = wy * 16 + (lane >> 2);
    int p0 = lane & 3;

    for (int kc = 0; kc < 8; kc++) {
        int b = kc & 1;
        if (kc + 1 < 8) {
            stage(sb, b ^ 1, kc + 1, n0, N, t);
            asm volatile("cp.async.wait_group 1;");
        } else {
            asm volatile("cp.async.wait_group 0;");
        }
        __syncthreads();

        const char* ag = sm + AGO(b);
        const char* af = sm + AFO(b);
        const char* bw = sm + BWO(b);
        const char* bs = sm + BSO(b);

        // A fragments: half2 at [row][k], row stride 48 B, k0 = p0*2
        unsigned aG0 = *(const unsigned*)(ag + r0 * 48 + p0 * 4);
        unsigned aG1 = *(const unsigned*)(ag + (r0 + 8) * 48 + p0 * 4);
        unsigned aG2 = *(const unsigned*)(ag + r0 * 48 + p0 * 4 + 16);
        unsigned aG3 = *(const unsigned*)(ag + (r0 + 8) * 48 + p0 * 4 + 16);
        unsigned aF0 = *(const unsigned*)(af + r0 * 48 + p0 * 4);
        unsigned aF1 = *(const unsigned*)(af + (r0 + 8) * 48 + p0 * 4);
        unsigned aF2 = *(const unsigned*)(af + r0 * 48 + p0 * 4 + 16);
        unsigned aF3 = *(const unsigned*)(af + (r0 + 8) * 48 + p0 * 4 + 16);

#pragma unroll
        for (int ni = 0; ni < 8; ni++) {
            int n = wx * 64 + ni * 8 + (lane >> 2);
            uint2 wv = *(const uint2*)(bw + p0 * 2080 + n * 8);
            mma_f16(accG[ni], aG0, aG1, aG2, aG3, wv.x, wv.y);
            uint2 sv = *(const uint2*)(bs + p0 * 2080 + n * 8);
            mma_f16(accS[ni], aF0, aF1, aF2, aF3, sv.x, sv.y);
        }
        __syncthreads();
    }

    // ---- epilogue ----
    float2* sLN = (float2*)sm;           // [32 rows][4 wx]
    int colb = wx * 64 + 2 * p0;

#pragma unroll
    for (int ni = 0; ni < 8; ni++) {
        float2 bb = *(const float2*)(bias + colb + ni * 8);
        float2 sv = *(const float2*)(sbias + colb + ni * 8);
        accG[ni][0] += bb.x; accG[ni][1] += bb.y;
        accG[ni][2] += bb.x; accG[ni][3] += bb.y;
        accS[ni][0] += sv.x; accS[ni][1] += sv.y;
        accS[ni][2] += sv.x; accS[ni][3] += sv.y;
    }

    float s1 = 0.f, q1 = 0.f, s2 = 0.f, q2 = 0.f;
#pragma unroll
    for (int ni = 0; ni < 8; ni++) {
        s1 += accG[ni][0] + accG[ni][1];
        q1 += accG[ni][0] * accG[ni][0] + accG[ni][1] * accG[ni][1];
        s2 += accG[ni][2] + accG[ni][3];
        q2 += accG[ni][2] * accG[ni][2] + accG[ni][3] * accG[ni][3];
    }
#pragma unroll
    for (int off = 1; off <= 2; off <<= 1) {
        s1 += __shfl_xor_sync(0xffffffffu, s1, off);
        q1 += __shfl_xor_sync(0xffffffffu, q1, off);
        s2 += __shfl_xor_sync(0xffffffffu, s2, off);
        q2 += __shfl_xor_sync(0xffffffffu, q2, off);
    }
    if (p0 == 0) {
        sLN[r0 * 4 + wx] = make_float2(s1, q1);
        sLN[(r0 + 8) * 4 + wx] = make_float2(s2, q2);
    }
    __syncthreads();
    float2 t0 = sLN[r0 * 4 + 0], t1 = sLN[r0 * 4 + 1];
    float2 t2 = sLN[r0 * 4 + 2], t3 = sLN[r0 * 4 + 3];
    float mu1 = (t0.x + t1.x + t2.x + t3.x) * (1.0f / HD);
    float var1 = (t0.y + t1.y + t2.y + t3.y) * (1.0f / HD) - mu1 * mu1;
    float inv1 = rsqrtf(var1 + 1e-5f);
    float2 u0 = sLN[(r0 + 8) * 4 + 0], u1 = sLN[(r0 + 8) * 4 + 1];
    float2 u2 = sLN[(r0 + 8) * 4 + 2], u3 = sLN[(r0 + 8) * 4 + 3];
    float mu2 = (u0.x + u1.x + u2.x + u3.x) * (1.0f / HD);
    float var2 = (u0.y + u1.y + u2.y + u3.y) * (1.0f / HD) - mu2 * mu2;
    float inv2 = rsqrtf(var2 + 1e-5f);

    int node1 = n0 + r0, node2 = n0 + r0 + 8;
#pragma unroll
    for (int ni = 0; ni < 8; ni++) {
        int col = colb + ni * 8;
        float2 gm = *(const float2*)(gamma + col);
        float2 bt = *(const float2*)(beta + col);
        if (node1 < N) {
            float2 o;
            o.x = fmaxf((accG[ni][0] - mu1) * inv1 * gm.x + bt.x, 0.f) + accS[ni][0];
            o.y = fmaxf((accG[ni][1] - mu1) * inv1 * gm.y + bt.y, 0.f) + accS[ni][1];
            *(float2*)(out + (size_t)node1 * HD + col) = o;
        }
        if (node2 < N) {
            float2 o;
            o.x = fmaxf((accG[ni][2] - mu2) * inv2 * gm.x + bt.x, 0.f) + accS[ni][2];
            o.y = fmaxf((accG[ni][3] - mu2) * inv2 * gm.y + bt.y, 0.f) + accS[ni][3];
            *(float2*)(out + (size_t)node2 * HD + col) = o;
        }
    }
}

// ---------------------------------------------------------------------------
extern "C" void kernel_launch(void* const* d_in, const int* in_sizes, int n_in,
                              void* d_out, int out_size)
{
    const float* feat = (const float*)d_in[0];
    const void*  src  = d_in[1];
    const void*  dst  = d_in[2];
    const float* Wm   = (const float*)d_in[3];
    const float* bv   = (const float*)d_in[4];
    const float* gm   = (const float*)d_in[5];
    const float* bt   = (const float*)d_in[6];
    const float* sWm  = (const float*)d_in[7];
    const float* sbv  = (const float*)d_in[8];
    float* out = (float*)d_out;

    int N = in_sizes[0] / FD;
    int E = in_sizes[1];
    int nb = (N + 1023) / 1024;

    k_init<<<(N + 255) / 256, 256>>>((const int*)src, E, N);
    k_count<<<(E / 2 + 255) / 256, 256>>>(src, dst, E);
    k_scan1<<<nb, 1024>>>(N);
    k_scan3<<<nb, 1024>>>(N, E);
    k_h16<<<(N * 8 + 255) / 256, 256>>>(feat, N);
    k_fill<<<(E + 255) / 256, 256>>>(src, dst, E);
    k_gather<<<(N * 32 + 255) / 256, 256>>>(N);
    k_prep<<<(32 * 256 + 255) / 256, 256>>>(Wm, sWm);

    cudaFuncSetAttribute(k_fused, cudaFuncAttributeMaxDynamicSharedMemorySize, SMTOT);
    k_fused<<<(N + 31) / 32, 256, SMTOT>>>(bv, gm, bt, sbv, out, N);
}

// round 10
// speedup vs baseline: 3.7647x; 1.1350x over previous
#include <cuda_runtime.h>
#include <cuda_fp16.h>
#include <stdint.h>

#define NN 100000
#define EMAX 1700000
#define FD 128
#define HD 256

// ---------------- scratch (__device__ globals; no allocs allowed) ----------
__device__ int    g_deg_out[NN];
__device__ int    g_deg_in[NN];
__device__ int    g_is64;
__device__ float  g_nsrc[NN];
__device__ float  g_ndst[NN];
__device__ int    g_rowptr[NN + 1];
__device__ int    g_cursor[NN];
__device__ int    g_bsum[128];
__device__ int    g_eidx[EMAX];
__device__ __half g_h16[(size_t)NN * FD];   // feat * norm_src (fp16), for gather
__device__ __half g_a16[(size_t)NN * FD];   // agg (fp16), A of GCN gemm
__device__ __half g_f16[(size_t)NN * FD];   // raw feat (fp16), A of skip gemm
// B packed for m16n8k16: [(kc*4+p0)*256 + n] -> uint2{half2(k0,k0+1), half2(k0+8,k0+9)}
__device__ uint2  g_W16[32 * 256];
__device__ uint2  g_S16[32 * 256];

// ---------------------------------------------------------------------------
__global__ void k_init(const int* __restrict__ srcw, int E, int N) {
    int i = blockIdx.x * blockDim.x + threadIdx.x;
    if (i < N) { g_deg_out[i] = 0; g_deg_in[i] = 0; }
    if (blockIdx.x == 0) {
        __shared__ int bad;
        if (threadIdx.x == 0) bad = 0;
        __syncthreads();
        int n = E / 2; if (n > 256) n = 256;
        if ((int)threadIdx.x < n && srcw[2 * threadIdx.x + 1] != 0) bad = 1;
        __syncthreads();
        if (threadIdx.x == 0) g_is64 = (bad == 0);
    }
}

__device__ __forceinline__ int load_idx(const void* p, int i) {
    if (g_is64) return (int)((const long long*)p)[i];
    return ((const int*)p)[i];
}

// 2 edges per thread, vector loads
__global__ void k_count(const void* __restrict__ src, const void* __restrict__ dst, int E) {
    int i = (blockIdx.x * blockDim.x + threadIdx.x) * 2;
    if (i >= E) return;
    int s0, s1, d0, d1;
    bool two = (i + 1 < E);
    if (g_is64) {
        if (two) {
            longlong2 sv = *(const longlong2*)((const long long*)src + i);
            longlong2 dv = *(const longlong2*)((const long long*)dst + i);
            s0 = (int)sv.x; s1 = (int)sv.y; d0 = (int)dv.x; d1 = (int)dv.y;
        } else {
            s0 = (int)((const long long*)src)[i]; d0 = (int)((const long long*)dst)[i];
            s1 = 0; d1 = 0;
        }
    } else {
        if (two) {
            int2 sv = *(const int2*)((const int*)src + i);
            int2 dv = *(const int2*)((const int*)dst + i);
            s0 = sv.x; s1 = sv.y; d0 = dv.x; d1 = dv.y;
        } else {
            s0 = ((const int*)src)[i]; d0 = ((const int*)dst)[i];
            s1 = 0; d1 = 0;
        }
    }
    atomicAdd(&g_deg_out[s0], 1);
    atomicAdd(&g_deg_in[d0], 1);
    if (two) {
        atomicAdd(&g_deg_out[s1], 1);
        atomicAdd(&g_deg_in[d1], 1);
    }
}

__global__ void k_scan1(int N) {
    __shared__ int s[1024];
    int tid = threadIdx.x;
    int i = blockIdx.x * 1024 + tid;
    int v = 0;
    if (i < N) {
        int din = g_deg_in[i];
        v = din;
        g_nsrc[i] = rsqrtf(fmaxf((float)g_deg_out[i], 1.0f));
        g_ndst[i] = rsqrtf(fmaxf((float)din, 1.0f));
    }
    s[tid] = v;
    for (int off = 1; off < 1024; off <<= 1) {
        __syncthreads();
        int t = (tid >= off) ? s[tid - off] : 0;
        __syncthreads();
        s[tid] += t;
    }
    __syncthreads();
    if (i < N) g_rowptr[i] = s[tid] - v;
    if (tid == 1023) g_bsum[blockIdx.x] = s[1023];
}

__global__ void k_scan3(int N, int E) {
    __shared__ int ssum;
    int tid = threadIdx.x;
    if (tid == 0) ssum = 0;
    __syncthreads();
    if (tid < blockIdx.x) atomicAdd(&ssum, g_bsum[tid]);
    __syncthreads();
    int i = blockIdx.x * 1024 + tid;
    if (i < N) {
        int val = g_rowptr[i] + ssum;
        g_rowptr[i] = val;
        g_cursor[i] = val;
    }
    if (i == 0) g_rowptr[N] = E;
}

// merged: blocks [0, FB) do CSR fill; blocks [FB, ...) build h16/f16 tables
__global__ void k_fill_h16(const void* __restrict__ src, const void* __restrict__ dst,
                           const float* __restrict__ feat, int E, int N, int FB) {
    if ((int)blockIdx.x < FB) {
        int i = blockIdx.x * blockDim.x + threadIdx.x;
        if (i < E) {
            int d = load_idx(dst, i);
            int pos = atomicAdd(&g_cursor[d], 1);
            g_eidx[pos] = load_idx(src, i);
        }
    } else {
        int i = (blockIdx.x - FB) * blockDim.x + threadIdx.x;
        if (i >= N * 8) return;
        int node = i >> 3, seg = i & 7;
        float ns = g_nsrc[node];
        const float4* fp = (const float4*)(feat + (size_t)node * FD + seg * 16);
        __half2 o[8], f[8];
#pragma unroll
        for (int j = 0; j < 4; j++) {
            float4 v = fp[j];
            o[j * 2]     = __floats2half2_rn(v.x * ns, v.y * ns);
            o[j * 2 + 1] = __floats2half2_rn(v.z * ns, v.w * ns);
            f[j * 2]     = __floats2half2_rn(v.x, v.y);
            f[j * 2 + 1] = __floats2half2_rn(v.z, v.w);
        }
        size_t off = (size_t)node * FD + seg * 16;
        *(uint4*)(g_h16 + off)     = *(uint4*)&o[0];
        *(uint4*)(g_h16 + off + 8) = *(uint4*)&o[4];
        *(uint4*)(g_f16 + off)     = *(uint4*)&f[0];
        *(uint4*)(g_f16 + off + 8) = *(uint4*)&f[4];
    }
}

// warp per node: a16[n] = fp16(norm_dst[n] * sum h16[src_e])
__global__ void k_gather(int N) {
    int w = (blockIdx.x * blockDim.x + threadIdx.x) >> 5;
    int lane = threadIdx.x & 31;
    if (w >= N) return;
    int beg = g_rowptr[w], end = g_rowptr[w + 1];
    float4 acc = make_float4(0.f, 0.f, 0.f, 0.f);
    for (int base = beg; base < end; base += 32) {
        int idx = base + lane;
        int mye = (idx < end) ? g_eidx[idx] : 0;
        int cnt = min(32, end - base);
        for (int i = 0; i < cnt; i++) {
            int s = __shfl_sync(0xffffffffu, mye, i);
            uint2 hv = *(const uint2*)(g_h16 + (size_t)s * FD + (lane << 2));
            float2 f0 = __half22float2(*(__half2*)&hv.x);
            float2 f1 = __half22float2(*(__half2*)&hv.y);
            acc.x += f0.x; acc.y += f0.y; acc.z += f1.x; acc.w += f1.y;
        }
    }
    float nd = g_ndst[w];
    __half2 o0 = __floats2half2_rn(acc.x * nd, acc.y * nd);
    __half2 o1 = __floats2half2_rn(acc.z * nd, acc.w * nd);
    uint2 ov = make_uint2(*(unsigned*)&o0, *(unsigned*)&o1);
    *(uint2*)(g_a16 + (size_t)w * FD + (lane << 2)) = ov;
}

// pack weights fp16 for m16n8k16 B fragments
__global__ void k_prep(const float* __restrict__ W, const float* __restrict__ sW) {
    int i = blockIdx.x * blockDim.x + threadIdx.x;  // 0..8191
    if (i >= 32 * 256) return;
    int kc = i >> 10, p0 = (i >> 8) & 3, n = i & 255;
    int k0 = kc * 16 + p0 * 2;
    __half2 w0 = __floats2half2_rn(W[k0 * HD + n],       W[(k0 + 1) * HD + n]);
    __half2 w1 = __floats2half2_rn(W[(k0 + 8) * HD + n], W[(k0 + 9) * HD + n]);
    g_W16[i] = make_uint2(*(unsigned*)&w0, *(unsigned*)&w1);
    __half2 s0 = __floats2half2_rn(sW[k0 * HD + n],       sW[(k0 + 1) * HD + n]);
    __half2 s1 = __floats2half2_rn(sW[(k0 + 8) * HD + n], sW[(k0 + 9) * HD + n]);
    g_S16[i] = make_uint2(*(unsigned*)&s0, *(unsigned*)&s1);
}

// ---------------------------------------------------------------------------
__device__ __forceinline__ void mma_f16(float* c, unsigned a0, unsigned a1,
                                        unsigned a2, unsigned a3,
                                        unsigned b0, unsigned b1) {
    asm volatile(
        "mma.sync.aligned.m16n8k16.row.col.f32.f16.f16.f32 "
        "{%0,%1,%2,%3}, {%4,%5,%6,%7}, {%8,%9}, {%0,%1,%2,%3};"
        : "+f"(c[0]), "+f"(c[1]), "+f"(c[2]), "+f"(c[3])
        : "r"(a0), "r"(a1), "r"(a2), "r"(a3), "r"(b0), "r"(b1));
}

static __device__ __forceinline__ uint32_t smem_u32(const void* p) {
    uint32_t a;
    asm("{ .reg .u64 t; cvta.to.shared.u64 t, %1; cvt.u32.u64 %0, t; }"
        : "=r"(a) : "l"(p));
    return a;
}

// Persistent fused kernel smem layout (bytes):
//  B_w  [32][260 uint2] = 66560 at 0
//  B_s  66560 at 66560                         (weights resident, loaded once)
//  A buffers: 2 x { A_agg [64][272B], A_feat [64][272B] } = 2 x 34816
//  sLN  [64][4] float2 = 2048
#define BW_OFF   0
#define BS_OFF   66560
#define ABUF(b)  (133120 + (b) * 34816)
#define AG(b)    (ABUF(b))
#define AF(b)    (ABUF(b) + 17408)
#define SLN_OFF  202752
#define SMTOT    204800

// stage A for tile (64 rows x 128 halves, both matrices): 2048 16B chunks / 512 thr
__device__ __forceinline__ void stageA(uint32_t sb, int b, int tile, int N, int t) {
    int n0 = tile * 64;
#pragma unroll
    for (int j = 0; j < 4; j++) {
        int c = t + (j << 9);                 // 0..2047
        int mat = c >> 10, row = (c >> 4) & 63, seg = c & 15;
        int node = n0 + row;
        int sz = (node < N) ? 16 : 0;
        const __half* srcp = (mat ? g_f16 : g_a16) + (size_t)node * FD + seg * 8;
        uint32_t dst = sb + (mat ? AF(b) : AG(b)) + row * 272 + seg * 16;
        asm volatile("cp.async.cg.shared.global [%0], [%1], 16, %2;"
                     :: "r"(dst), "l"(srcp), "r"(sz));
    }
    asm volatile("cp.async.commit_group;");
}

// Persistent dual-GEMM + LN + ReLU + skip-add. grid=148, 512 threads, occ 1.
// Tile 64 rows x 256 cols; 16 warps = 4 row-groups x 4 col-groups; warp 16x64.
__global__ __launch_bounds__(512, 1)
void k_fused(const float* __restrict__ bias, const float* __restrict__ gamma,
             const float* __restrict__ beta, const float* __restrict__ sbias,
             float* __restrict__ out, int N, int ntiles)
{
    extern __shared__ char sm[];
    uint32_t sb = smem_u32(sm);
    int t = threadIdx.x;
    int lane = t & 31, wid = t >> 5;
    int wy = wid >> 2, wx = wid & 3;         // wy 0..3 rows, wx 0..3 cols
    int r0 = wy * 16 + (lane >> 2);
    int p0 = lane & 3;

    // ---- load both packed weight matrices into smem once (8192 chunks) ----
#pragma unroll
    for (int j = 0; j < 16; j++) {
        int c = t + (j << 9);                 // 0..8191
        int mat = c >> 12, r = (c >> 7) & 31, col2 = (c & 127) * 2;
        const uint2* srcp = (mat ? g_S16 : g_W16) + r * 256 + col2;
        uint32_t dst = sb + (mat ? BS_OFF : BW_OFF) + r * 2080 + col2 * 8;
        asm volatile("cp.async.ca.shared.global [%0], [%1], 16;"
                     :: "r"(dst), "l"(srcp));
    }
    asm volatile("cp.async.commit_group;");

    int tile0 = blockIdx.x;
    if (tile0 < ntiles) stageA(sb, 0, tile0, N, t);
    else asm volatile("cp.async.commit_group;");

    const char* bw = sm + BW_OFF;
    const char* bs = sm + BS_OFF;
    float2* sLN = (float2*)(sm + SLN_OFF);

    int it = 0;
    for (int tile = tile0; tile < ntiles; tile += gridDim.x, it++) {
        int b = it & 1;
        int nxt = tile + gridDim.x;
        if (nxt < ntiles) {
            stageA(sb, b ^ 1, nxt, N, t);
            asm volatile("cp.async.wait_group 1;");
        } else {
            asm volatile("cp.async.wait_group 0;");
        }
        __syncthreads();

        const char* ag = sm + AG(b);
        const char* af = sm + AF(b);

        float accG[8][4], accS[8][4];
#pragma unroll
        for (int i = 0; i < 8; i++)
#pragma unroll
            for (int j = 0; j < 4; j++) { accG[i][j] = 0.f; accS[i][j] = 0.f; }

#pragma unroll
        for (int kc = 0; kc < 8; kc++) {
            int ko = kc * 32 + p0 * 4;        // byte offset of half2(k0,k0+1)
            unsigned aG0 = *(const unsigned*)(ag + r0 * 272 + ko);
            unsigned aG1 = *(const unsigned*)(ag + (r0 + 8) * 272 + ko);
            unsigned aG2 = *(const unsigned*)(ag + r0 * 272 + ko + 16);
            unsigned aG3 = *(const unsigned*)(ag + (r0 + 8) * 272 + ko + 16);
            unsigned aF0 = *(const unsigned*)(af + r0 * 272 + ko);
            unsigned aF1 = *(const unsigned*)(af + (r0 + 8) * 272 + ko);
            unsigned aF2 = *(const unsigned*)(af + r0 * 272 + ko + 16);
            unsigned aF3 = *(const unsigned*)(af + (r0 + 8) * 272 + ko + 16);
#pragma unroll
            for (int ni = 0; ni < 8; ni++) {
                int n = wx * 64 + ni * 8 + (lane >> 2);
                uint2 wv = *(const uint2*)(bw + (kc * 4 + p0) * 2080 + n * 8);
                mma_f16(accG[ni], aG0, aG1, aG2, aG3, wv.x, wv.y);
                uint2 sv = *(const uint2*)(bs + (kc * 4 + p0) * 2080 + n * 8);
                mma_f16(accS[ni], aF0, aF1, aF2, aF3, sv.x, sv.y);
            }
        }

        // ---- epilogue ----
        int colb = wx * 64 + 2 * p0;
#pragma unroll
        for (int ni = 0; ni < 8; ni++) {
            float2 bb = *(const float2*)(bias + colb + ni * 8);
            float2 sv = *(const float2*)(sbias + colb + ni * 8);
            accG[ni][0] += bb.x; accG[ni][1] += bb.y;
            accG[ni][2] += bb.x; accG[ni][3] += bb.y;
            accS[ni][0] += sv.x; accS[ni][1] += sv.y;
            accS[ni][2] += sv.x; accS[ni][3] += sv.y;
        }

        float s1 = 0.f, q1 = 0.f, s2 = 0.f, q2 = 0.f;
#pragma unroll
        for (int ni = 0; ni < 8; ni++) {
            s1 += accG[ni][0] + accG[ni][1];
            q1 += accG[ni][0] * accG[ni][0] + accG[ni][1] * accG[ni][1];
            s2 += accG[ni][2] + accG[ni][3];
            q2 += accG[ni][2] * accG[ni][2] + accG[ni][3] * accG[ni][3];
        }
#pragma unroll
        for (int off = 1; off <= 2; off <<= 1) {
            s1 += __shfl_xor_sync(0xffffffffu, s1, off);
            q1 += __shfl_xor_sync(0xffffffffu, q1, off);
            s2 += __shfl_xor_sync(0xffffffffu, s2, off);
            q2 += __shfl_xor_sync(0xffffffffu, q2, off);
        }
        if (p0 == 0) {
            sLN[r0 * 4 + wx] = make_float2(s1, q1);
            sLN[(r0 + 8) * 4 + wx] = make_float2(s2, q2);
        }
        __syncthreads();
        float2 t0 = sLN[r0 * 4 + 0], t1 = sLN[r0 * 4 + 1];
        float2 t2 = sLN[r0 * 4 + 2], t3 = sLN[r0 * 4 + 3];
        float mu1 = (t0.x + t1.x + t2.x + t3.x) * (1.0f / HD);
        float var1 = (t0.y + t1.y + t2.y + t3.y) * (1.0f / HD) - mu1 * mu1;
        float inv1 = rsqrtf(var1 + 1e-5f);
        float2 u0 = sLN[(r0 + 8) * 4 + 0], u1 = sLN[(r0 + 8) * 4 + 1];
        float2 u2 = sLN[(r0 + 8) * 4 + 2], u3 = sLN[(r0 + 8) * 4 + 3];
        float mu2 = (u0.x + u1.x + u2.x + u3.x) * (1.0f / HD);
        float var2 = (u0.y + u1.y + u2.y + u3.y) * (1.0f / HD) - mu2 * mu2;
        float inv2 = rsqrtf(var2 + 1e-5f);

        int node1 = tile * 64 + r0, node2 = node1 + 8;
#pragma unroll
        for (int ni = 0; ni < 8; ni++) {
            int col = colb + ni * 8;
            float2 gm = *(const float2*)(gamma + col);
            float2 bt = *(const float2*)(beta + col);
            if (node1 < N) {
                float2 o;
                o.x = fmaxf((accG[ni][0] - mu1) * inv1 * gm.x + bt.x, 0.f) + accS[ni][0];
                o.y = fmaxf((accG[ni][1] - mu1) * inv1 * gm.y + bt.y, 0.f) + accS[ni][1];
                *(float2*)(out + (size_t)node1 * HD + col) = o;
            }
            if (node2 < N) {
                float2 o;
                o.x = fmaxf((accG[ni][2] - mu2) * inv2 * gm.x + bt.x, 0.f) + accS[ni][2];
                o.y = fmaxf((accG[ni][3] - mu2) * inv2 * gm.y + bt.y, 0.f) + accS[ni][3];
                *(float2*)(out + (size_t)node2 * HD + col) = o;
            }
        }
        __syncthreads();   // protect A buffer b before next iteration stages into it
    }
}

// ---------------------------------------------------------------------------
extern "C" void kernel_launch(void* const* d_in, const int* in_sizes, int n_in,
                              void* d_out, int out_size)
{
    const float* feat = (const float*)d_in[0];
    const void*  src  = d_in[1];
    const void*  dst  = d_in[2];
    const float* Wm   = (const float*)d_in[3];
    const float* bv   = (const float*)d_in[4];
    const float* gm   = (const float*)d_in[5];
    const float* bt   = (const float*)d_in[6];
    const float* sWm  = (const float*)d_in[7];
    const float* sbv  = (const float*)d_in[8];
    float* out = (float*)d_out;

    int N = in_sizes[0] / FD;
    int E = in_sizes[1];
    int nb = (N + 1023) / 1024;
    int FB = (E + 255) / 256;
    int HB = (N * 8 + 255) / 256;

    k_init<<<(N + 255) / 256, 256>>>((const int*)src, E, N);
    k_count<<<(E / 2 + 255) / 256, 256>>>(src, dst, E);
    k_scan1<<<nb, 1024>>>(N);
    k_scan3<<<nb, 1024>>>(N, E);
    k_fill_h16<<<FB + HB, 256>>>(src, dst, feat, E, N, FB);
    k_gather<<<(N * 32 + 255) / 256, 256>>>(N);
    k_prep<<<(32 * 256 + 255) / 256, 256>>>(Wm, sWm);

    int ntiles = (N + 63) / 64;
    cudaFuncSetAttribute(k_fused, cudaFuncAttributeMaxDynamicSharedMemorySize, SMTOT);
    k_fused<<<148, 512, SMTOT>>>(bv, gm, bt, sbv, out, N, ntiles);
}